// round 2
// baseline (speedup 1.0000x reference)
#include <cuda_runtime.h>
#include <math.h>

#define S 4096
#define D 1024
#define H 16
#define DH 64
#define F 4096
#define EPSF 1e-6f

// ---------------- scratch (device globals: alloc-free) ----------------
__device__ float g_xn[S * D];
__device__ float g_h [S * F];
__device__ float g_q [S * D];
__device__ float g_k [S * D];
__device__ float g_v [S * D];
__device__ float g_o [S * D];

// ---------------- LayerNorm over D=1024, block per row ----------------
__global__ void ln_kernel(const float* __restrict__ x,
                          const float* __restrict__ gamma,
                          const float* __restrict__ beta,
                          float* __restrict__ y) {
    __shared__ float sh[8];
    __shared__ float stat;
    int row = blockIdx.x;
    int t = threadIdx.x;
    const float4* xr = (const float4*)(x + (size_t)row * D);
    float4 xv = xr[t];

    float s = xv.x + xv.y + xv.z + xv.w;
#pragma unroll
    for (int o = 16; o > 0; o >>= 1) s += __shfl_xor_sync(0xffffffffu, s, o);
    if ((t & 31) == 0) sh[t >> 5] = s;
    __syncthreads();
    if (t == 0) {
        float tot = 0.f;
#pragma unroll
        for (int i = 0; i < 8; i++) tot += sh[i];
        stat = tot * (1.f / (float)D);
    }
    __syncthreads();
    float mean = stat;

    float d0 = xv.x - mean, d1 = xv.y - mean, d2 = xv.z - mean, d3 = xv.w - mean;
    float sq = d0 * d0 + d1 * d1 + d2 * d2 + d3 * d3;
#pragma unroll
    for (int o = 16; o > 0; o >>= 1) sq += __shfl_xor_sync(0xffffffffu, sq, o);
    __syncthreads();           // protect sh reuse
    if ((t & 31) == 0) sh[t >> 5] = sq;
    __syncthreads();
    if (t == 0) {
        float tot = 0.f;
#pragma unroll
        for (int i = 0; i < 8; i++) tot += sh[i];
        stat = rsqrtf(tot * (1.f / (float)D) + EPSF);
    }
    __syncthreads();
    float rinv = stat;

    float4 gv = ((const float4*)gamma)[t];
    float4 bv = ((const float4*)beta)[t];
    float4 o4;
    o4.x = d0 * rinv * gv.x + bv.x;
    o4.y = d1 * rinv * gv.y + bv.y;
    o4.z = d2 * rinv * gv.z + bv.z;
    o4.w = d3 * rinv * gv.w + bv.w;
    ((float4*)(y + (size_t)row * D))[t] = o4;
}

// ---------------- per-head LN (Dh=64, no bias), thread per row ----------------
__global__ void qknorm_kernel(float* __restrict__ tq, const float* __restrict__ scale) {
    int row = blockIdx.x * blockDim.x + threadIdx.x;   // S*H rows exactly
    float* p = tq + (size_t)row * DH;
    float4 v[16];
    float s = 0.f;
#pragma unroll
    for (int i = 0; i < 16; i++) {
        v[i] = ((const float4*)p)[i];
        s += v[i].x + v[i].y + v[i].z + v[i].w;
    }
    float mean = s * (1.f / (float)DH);
    float sq = 0.f;
#pragma unroll
    for (int i = 0; i < 16; i++) {
        v[i].x -= mean; v[i].y -= mean; v[i].z -= mean; v[i].w -= mean;
        sq += v[i].x * v[i].x + v[i].y * v[i].y + v[i].z * v[i].z + v[i].w * v[i].w;
    }
    float r = rsqrtf(sq * (1.f / (float)DH) + EPSF);
#pragma unroll
    for (int i = 0; i < 16; i++) {
        float4 sc = ((const float4*)scale)[i];
        float4 o4;
        o4.x = v[i].x * r * sc.x;
        o4.y = v[i].y * r * sc.y;
        o4.z = v[i].z * r * sc.z;
        o4.w = v[i].w * r * sc.w;
        ((float4*)p)[i] = o4;
    }
}

// ---------------- GELU (tanh approx, matches jax.nn.gelu default) ----------------
__device__ __forceinline__ float gelu_f(float x) {
    float x3 = x * x * x;
    return 0.5f * x * (1.f + tanhf(0.7978845608028654f * (x + 0.044715f * x3)));
}

// ---------------- SGEMM: C = epilogue(A[M,K] @ B[K,N]) ----------------
// MODE 0: C = acc + bias    MODE 1: C = gelu(acc + bias)    MODE 2: C += acc
template <int MODE>
__global__ void __launch_bounds__(256) sgemm_kernel(
    const float* __restrict__ A, const float* __restrict__ B,
    const float* __restrict__ bias, float* __restrict__ C,
    int M, int N, int K)
{
    __shared__ float As[8][128];
    __shared__ float Bs[8][128];
    int tid = threadIdx.x;
    int bm = blockIdx.y << 7, bn = blockIdx.x << 7;

    int arow = tid >> 1,  acol = (tid & 1) << 2;   // 128 x 8 A tile
    int brow = tid >> 5,  bcol = (tid & 31) << 2;  // 8 x 128 B tile
    int tm = (tid >> 4) << 3, tn = (tid & 15) << 3;

    const float* Ap = A + (size_t)(bm + arow) * K + acol;
    const float* Bp = B + (size_t)brow * N + bn + bcol;

    float acc[8][8];
#pragma unroll
    for (int i = 0; i < 8; i++)
#pragma unroll
        for (int j = 0; j < 8; j++) acc[i][j] = 0.f;

    int nk = K >> 3;
    for (int kb = 0; kb < nk; kb++) {
        float4 a4 = *(const float4*)Ap;
        float4 b4 = *(const float4*)Bp;
        As[acol + 0][arow] = a4.x;
        As[acol + 1][arow] = a4.y;
        As[acol + 2][arow] = a4.z;
        As[acol + 3][arow] = a4.w;
        *(float4*)&Bs[brow][bcol] = b4;
        __syncthreads();
#pragma unroll
        for (int kk = 0; kk < 8; kk++) {
            float ra[8], rb[8];
            *(float4*)&ra[0] = *(float4*)&As[kk][tm];
            *(float4*)&ra[4] = *(float4*)&As[kk][tm + 4];
            *(float4*)&rb[0] = *(float4*)&Bs[kk][tn];
            *(float4*)&rb[4] = *(float4*)&Bs[kk][tn + 4];
#pragma unroll
            for (int i = 0; i < 8; i++)
#pragma unroll
                for (int j = 0; j < 8; j++) acc[i][j] += ra[i] * rb[j];
        }
        __syncthreads();
        Ap += 8;
        Bp += (size_t)8 * N;
    }

#pragma unroll
    for (int i = 0; i < 8; i++) {
        float* cp = C + (size_t)(bm + tm + i) * N + bn + tn;
        if (MODE == 2) {
            float4 c0 = *(float4*)cp;
            float4 c1 = *(float4*)(cp + 4);
            c0.x += acc[i][0]; c0.y += acc[i][1]; c0.z += acc[i][2]; c0.w += acc[i][3];
            c1.x += acc[i][4]; c1.y += acc[i][5]; c1.z += acc[i][6]; c1.w += acc[i][7];
            *(float4*)cp = c0;
            *(float4*)(cp + 4) = c1;
        } else {
            const float* bp = bias + bn + tn;
            float4 bb0 = *(const float4*)bp;
            float4 bb1 = *(const float4*)(bp + 4);
            float v0 = acc[i][0] + bb0.x, v1 = acc[i][1] + bb0.y;
            float v2 = acc[i][2] + bb0.z, v3 = acc[i][3] + bb0.w;
            float v4 = acc[i][4] + bb1.x, v5 = acc[i][5] + bb1.y;
            float v6 = acc[i][6] + bb1.z, v7 = acc[i][7] + bb1.w;
            if (MODE == 1) {
                v0 = gelu_f(v0); v1 = gelu_f(v1); v2 = gelu_f(v2); v3 = gelu_f(v3);
                v4 = gelu_f(v4); v5 = gelu_f(v5); v6 = gelu_f(v6); v7 = gelu_f(v7);
            }
            float4 c0 = {v0, v1, v2, v3};
            float4 c1 = {v4, v5, v6, v7};
            *(float4*)cp = c0;
            *(float4*)(cp + 4) = c1;
        }
    }
}

// ---------------- causal flash attention, thread per (head, query) ----------------
__global__ void __launch_bounds__(128) attn_kernel(
    const float* __restrict__ q, const float* __restrict__ k,
    const float* __restrict__ v, float* __restrict__ o)
{
    __shared__ float Ks[64][64];
    __shared__ float Vs[64][64];
    int head = blockIdx.y;
    int qi = blockIdx.x * 128 + threadIdx.x;

    float qr[64];
    const float* qp = q + (size_t)qi * D + head * DH;
#pragma unroll
    for (int j = 0; j < 16; j++) {
        float4 t4 = ((const float4*)qp)[j];
        qr[4 * j + 0] = t4.x * 0.125f;   // 1/sqrt(Dh) folded into q
        qr[4 * j + 1] = t4.y * 0.125f;
        qr[4 * j + 2] = t4.z * 0.125f;
        qr[4 * j + 3] = t4.w * 0.125f;
    }

    float oa[64];
#pragma unroll
    for (int d = 0; d < 64; d++) oa[d] = 0.f;
    float m = -INFINITY, l = 0.f;

    int ntiles = blockIdx.x * 2 + 2;   // key tiles 0 .. 2*bx+1 (causal)
    int r = threadIdx.x >> 1;
    int c0 = (threadIdx.x & 1) * 32;

    for (int kt = 0; kt < ntiles; kt++) {
        const float* kp = k + (size_t)(kt * 64 + r) * D + head * DH + c0;
        const float* vp = v + (size_t)(kt * 64 + r) * D + head * DH + c0;
#pragma unroll
        for (int j = 0; j < 8; j++) {
            ((float4*)&Ks[r][c0])[j] = ((const float4*)kp)[j];
            ((float4*)&Vs[r][c0])[j] = ((const float4*)vp)[j];
        }
        __syncthreads();

        int jmax = qi - kt * 64 + 1;
        if (jmax > 64) jmax = 64;
        for (int j = 0; j < jmax; j++) {
            float s0 = 0.f, s1 = 0.f, s2 = 0.f, s3 = 0.f;
#pragma unroll
            for (int d = 0; d < 64; d += 4) {
                s0 += qr[d + 0] * Ks[j][d + 0];
                s1 += qr[d + 1] * Ks[j][d + 1];
                s2 += qr[d + 2] * Ks[j][d + 2];
                s3 += qr[d + 3] * Ks[j][d + 3];
            }
            float s = (s0 + s1) + (s2 + s3);
            float p;
            if (s > m) {
                float alpha = __expf(m - s);   // exp(-inf)=0 handles first key
#pragma unroll
                for (int d = 0; d < 64; d++) oa[d] *= alpha;
                l *= alpha;
                m = s;
                p = 1.f;
            } else {
                p = __expf(s - m);
            }
            l += p;
#pragma unroll
            for (int d = 0; d < 64; d++) oa[d] += p * Vs[j][d];
        }
        __syncthreads();
    }

    float inv = 1.f / l;
    float* op = o + (size_t)qi * D + head * DH;
#pragma unroll
    for (int j = 0; j < 16; j++) {
        float4 t4;
        t4.x = oa[4 * j + 0] * inv;
        t4.y = oa[4 * j + 1] * inv;
        t4.z = oa[4 * j + 2] * inv;
        t4.w = oa[4 * j + 3] * inv;
        ((float4*)op)[j] = t4;
    }
}

// ---------------- out = x + b_mo + b_ao (GEMMs then accumulate on top) ----------------
__global__ void init_out_kernel(const float* __restrict__ x,
                                const float* __restrict__ bmo,
                                const float* __restrict__ bao,
                                float* __restrict__ out) {
    int i = blockIdx.x * blockDim.x + threadIdx.x;
    int col = i & (D - 1);
    out[i] = x[i] + bmo[col] + bao[col];
}

// ---------------- launch ----------------
extern "C" void kernel_launch(void* const* d_in, const int* in_sizes, int n_in,
                              void* d_out, int out_size) {
    const float* x        = (const float*)d_in[0];
    // d_in[1] = mask: causal tril, implemented analytically -> ignored
    const float* ln_scale = (const float*)d_in[2];
    const float* ln_bias  = (const float*)d_in[3];
    const float* w_in     = (const float*)d_in[4];
    const float* b_in     = (const float*)d_in[5];
    const float* wq       = (const float*)d_in[6];
    const float* bq       = (const float*)d_in[7];
    const float* wk       = (const float*)d_in[8];
    const float* bk       = (const float*)d_in[9];
    const float* wv       = (const float*)d_in[10];
    const float* bv       = (const float*)d_in[11];
    const float* qn       = (const float*)d_in[12];
    const float* kn       = (const float*)d_in[13];
    const float* w_mo     = (const float*)d_in[14];
    const float* b_mo     = (const float*)d_in[15];
    const float* w_ao     = (const float*)d_in[16];
    const float* b_ao     = (const float*)d_in[17];
    float* out = (float*)d_out;

    float *xn, *h, *q, *k, *v, *o;
    cudaGetSymbolAddress((void**)&xn, g_xn);
    cudaGetSymbolAddress((void**)&h,  g_h);
    cudaGetSymbolAddress((void**)&q,  g_q);
    cudaGetSymbolAddress((void**)&k,  g_k);
    cudaGetSymbolAddress((void**)&v,  g_v);
    cudaGetSymbolAddress((void**)&o,  g_o);

    // 1. PreNorm
    ln_kernel<<<S, 256>>>(x, ln_scale, ln_bias, xn);

    // 2. MLP input + GELU: h = gelu(xn @ w_in + b_in)
    sgemm_kernel<1><<<dim3(F / 128, S / 128), 256>>>(xn, w_in, b_in, h, S, F, D);

    // 3. QKV projections
    sgemm_kernel<0><<<dim3(D / 128, S / 128), 256>>>(xn, wq, bq, q, S, D, D);
    sgemm_kernel<0><<<dim3(D / 128, S / 128), 256>>>(xn, wk, bk, k, S, D, D);
    sgemm_kernel<0><<<dim3(D / 128, S / 128), 256>>>(xn, wv, bv, v, S, D, D);

    // 4. qk-norm (per-head LN, no bias)
    qknorm_kernel<<<(S * H) / 256, 256>>>(q, qn);
    qknorm_kernel<<<(S * H) / 256, 256>>>(k, kn);

    // 5. causal attention
    attn_kernel<<<dim3(S / 128, H), 128>>>(q, k, v, o);

    // 6. out = x + b_mo + b_ao, then += h@w_mo, += o@w_ao
    init_out_kernel<<<(S * D) / 256, 256>>>(x, b_mo, b_ao, out);
    sgemm_kernel<2><<<dim3(D / 128, S / 128), 256>>>(h, w_mo, nullptr, out, S, D, F);
    sgemm_kernel<2><<<dim3(D / 128, S / 128), 256>>>(o, w_ao, nullptr, out, S, D, D);
}

// round 3
// speedup vs baseline: 1.0062x; 1.0062x over previous
#include <cuda_runtime.h>
#include <math.h>

#define S 4096
#define D 1024
#define H 16
#define DH 64
#define F 4096
#define EPSF 1e-6f

// ---------------- scratch (device globals: alloc-free) ----------------
__device__ float g_xn[S * D];
__device__ float g_h [S * F];
__device__ float g_q [S * D];
__device__ float g_k [S * D];
__device__ float g_v [S * D];
__device__ float g_o [S * D];

// ---------------- LayerNorm over D=1024, block per row ----------------
__global__ void ln_kernel(const float* __restrict__ x,
                          const float* __restrict__ gamma,
                          const float* __restrict__ beta,
                          float* __restrict__ y) {
    __shared__ float sh[8];
    __shared__ float stat;
    int row = blockIdx.x;
    int t = threadIdx.x;
    const float4* xr = (const float4*)(x + (size_t)row * D);
    float4 xv = xr[t];

    float s = xv.x + xv.y + xv.z + xv.w;
#pragma unroll
    for (int o = 16; o > 0; o >>= 1) s += __shfl_xor_sync(0xffffffffu, s, o);
    if ((t & 31) == 0) sh[t >> 5] = s;
    __syncthreads();
    if (t == 0) {
        float tot = 0.f;
#pragma unroll
        for (int i = 0; i < 8; i++) tot += sh[i];
        stat = tot * (1.f / (float)D);
    }
    __syncthreads();
    float mean = stat;

    float d0 = xv.x - mean, d1 = xv.y - mean, d2 = xv.z - mean, d3 = xv.w - mean;
    float sq = d0 * d0 + d1 * d1 + d2 * d2 + d3 * d3;
#pragma unroll
    for (int o = 16; o > 0; o >>= 1) sq += __shfl_xor_sync(0xffffffffu, sq, o);
    __syncthreads();
    if ((t & 31) == 0) sh[t >> 5] = sq;
    __syncthreads();
    if (t == 0) {
        float tot = 0.f;
#pragma unroll
        for (int i = 0; i < 8; i++) tot += sh[i];
        stat = rsqrtf(tot * (1.f / (float)D) + EPSF);
    }
    __syncthreads();
    float rinv = stat;

    float4 gv = ((const float4*)gamma)[t];
    float4 bv = ((const float4*)beta)[t];
    float4 o4;
    o4.x = d0 * rinv * gv.x + bv.x;
    o4.y = d1 * rinv * gv.y + bv.y;
    o4.z = d2 * rinv * gv.z + bv.z;
    o4.w = d3 * rinv * gv.w + bv.w;
    ((float4*)(y + (size_t)row * D))[t] = o4;
}

// ---------------- per-head LN (Dh=64, no bias), thread per row ----------------
__global__ void qknorm_kernel(float* __restrict__ tq, const float* __restrict__ scale) {
    int row = blockIdx.x * blockDim.x + threadIdx.x;
    float* p = tq + (size_t)row * DH;
    float4 v[16];
    float s = 0.f;
#pragma unroll
    for (int i = 0; i < 16; i++) {
        v[i] = ((const float4*)p)[i];
        s += v[i].x + v[i].y + v[i].z + v[i].w;
    }
    float mean = s * (1.f / (float)DH);
    float sq = 0.f;
#pragma unroll
    for (int i = 0; i < 16; i++) {
        v[i].x -= mean; v[i].y -= mean; v[i].z -= mean; v[i].w -= mean;
        sq += v[i].x * v[i].x + v[i].y * v[i].y + v[i].z * v[i].z + v[i].w * v[i].w;
    }
    float r = rsqrtf(sq * (1.f / (float)DH) + EPSF);
#pragma unroll
    for (int i = 0; i < 16; i++) {
        float4 sc = ((const float4*)scale)[i];
        float4 o4;
        o4.x = v[i].x * r * sc.x;
        o4.y = v[i].y * r * sc.y;
        o4.z = v[i].z * r * sc.z;
        o4.w = v[i].w * r * sc.w;
        ((float4*)p)[i] = o4;
    }
}

// ---------------- GELU (tanh approx, matches jax.nn.gelu default) ----------------
__device__ __forceinline__ float gelu_f(float x) {
    float x3 = x * x * x;
    return 0.5f * x * (1.f + tanhf(0.7978845608028654f * (x + 0.044715f * x3)));
}

// ---------------- double-buffered SGEMM: C = epilogue(A[M,K] @ B[K,N]) ----------------
// MODE 0: C = acc + bias    MODE 1: C = gelu(acc + bias)    MODE 2: C += acc
template <int MODE>
__global__ void __launch_bounds__(256, 2) sgemm_kernel(
    const float* __restrict__ A, const float* __restrict__ B,
    const float* __restrict__ bias, float* __restrict__ C,
    int M, int N, int K)
{
    __shared__ float As[2][8][132];   // [buf][k][m], padded to dodge STS conflicts
    __shared__ float Bs[2][8][128];   // [buf][k][n]
    int tid = threadIdx.x;
    int bm = blockIdx.y << 7, bn = blockIdx.x << 7;

    int arow = tid >> 1,  acol = (tid & 1) << 2;   // 128 x 8 A tile, 1 float4/thread
    int brow = tid >> 5,  bcol = (tid & 31) << 2;  // 8 x 128 B tile, 1 float4/thread
    int tm = (tid >> 4) << 3, tn = (tid & 15) << 3;

    const float* Ap = A + (size_t)(bm + arow) * K + acol;
    const float* Bp = B + (size_t)brow * N + bn + bcol;

    float acc[8][8];
#pragma unroll
    for (int i = 0; i < 8; i++)
#pragma unroll
        for (int j = 0; j < 8; j++) acc[i][j] = 0.f;

    // prologue: load tile 0 into buffer 0
    float4 a4 = *(const float4*)Ap;
    float4 b4 = *(const float4*)Bp;
    As[0][acol + 0][arow] = a4.x;
    As[0][acol + 1][arow] = a4.y;
    As[0][acol + 2][arow] = a4.z;
    As[0][acol + 3][arow] = a4.w;
    *(float4*)&Bs[0][brow][bcol] = b4;
    __syncthreads();

    int nk = K >> 3;
    for (int kb = 0; kb < nk; kb++) {
        int cur = kb & 1;
        // prefetch next tile from global while computing current
        if (kb + 1 < nk) {
            Ap += 8;
            Bp += (size_t)8 * N;
            a4 = *(const float4*)Ap;
            b4 = *(const float4*)Bp;
        }
#pragma unroll
        for (int kk = 0; kk < 8; kk++) {
            float ra[8], rb[8];
            *(float4*)&ra[0] = *(float4*)&As[cur][kk][tm];
            *(float4*)&ra[4] = *(float4*)&As[cur][kk][tm + 4];
            *(float4*)&rb[0] = *(float4*)&Bs[cur][kk][tn];
            *(float4*)&rb[4] = *(float4*)&Bs[cur][kk][tn + 4];
#pragma unroll
            for (int i = 0; i < 8; i++)
#pragma unroll
                for (int j = 0; j < 8; j++) acc[i][j] += ra[i] * rb[j];
        }
        if (kb + 1 < nk) {
            int nxt = cur ^ 1;
            As[nxt][acol + 0][arow] = a4.x;
            As[nxt][acol + 1][arow] = a4.y;
            As[nxt][acol + 2][arow] = a4.z;
            As[nxt][acol + 3][arow] = a4.w;
            *(float4*)&Bs[nxt][brow][bcol] = b4;
            __syncthreads();
        }
    }

#pragma unroll
    for (int i = 0; i < 8; i++) {
        float* cp = C + (size_t)(bm + tm + i) * N + bn + tn;
        if (MODE == 2) {
            float4 c0 = *(float4*)cp;
            float4 c1 = *(float4*)(cp + 4);
            c0.x += acc[i][0]; c0.y += acc[i][1]; c0.z += acc[i][2]; c0.w += acc[i][3];
            c1.x += acc[i][4]; c1.y += acc[i][5]; c1.z += acc[i][6]; c1.w += acc[i][7];
            *(float4*)cp = c0;
            *(float4*)(cp + 4) = c1;
        } else {
            const float* bp = bias + bn + tn;
            float4 bb0 = *(const float4*)bp;
            float4 bb1 = *(const float4*)(bp + 4);
            float v0 = acc[i][0] + bb0.x, v1 = acc[i][1] + bb0.y;
            float v2 = acc[i][2] + bb0.z, v3 = acc[i][3] + bb0.w;
            float v4 = acc[i][4] + bb1.x, v5 = acc[i][5] + bb1.y;
            float v6 = acc[i][6] + bb1.z, v7 = acc[i][7] + bb1.w;
            if (MODE == 1) {
                v0 = gelu_f(v0); v1 = gelu_f(v1); v2 = gelu_f(v2); v3 = gelu_f(v3);
                v4 = gelu_f(v4); v5 = gelu_f(v5); v6 = gelu_f(v6); v7 = gelu_f(v7);
            }
            float4 c0 = {v0, v1, v2, v3};
            float4 c1 = {v4, v5, v6, v7};
            *(float4*)cp = c0;
            *(float4*)(cp + 4) = c1;
        }
    }
}

// ---------------- causal flash attention, thread per (head, query) ----------------
// float4 smem reads (4x fewer LDS), 4-key chunks with one (rare) rescale per chunk
__global__ void __launch_bounds__(128) attn_kernel(
    const float* __restrict__ q, const float* __restrict__ k,
    const float* __restrict__ v, float* __restrict__ o)
{
    __shared__ float Ks[64][64];
    __shared__ float Vs[64][64];
    int head = blockIdx.y;
    int qi = blockIdx.x * 128 + threadIdx.x;

    float qr[64];
    const float* qp = q + (size_t)qi * D + head * DH;
#pragma unroll
    for (int j = 0; j < 16; j++) {
        float4 t4 = ((const float4*)qp)[j];
        qr[4 * j + 0] = t4.x * 0.125f;   // 1/sqrt(Dh) folded into q
        qr[4 * j + 1] = t4.y * 0.125f;
        qr[4 * j + 2] = t4.z * 0.125f;
        qr[4 * j + 3] = t4.w * 0.125f;
    }

    float oa[64];
#pragma unroll
    for (int d = 0; d < 64; d++) oa[d] = 0.f;
    float m = -INFINITY, l = 0.f;

    int ntiles = blockIdx.x * 2 + 2;   // key tiles 0 .. 2*bx+1 (causal)
    int r = threadIdx.x >> 1;
    int c0 = (threadIdx.x & 1) * 32;

    for (int kt = 0; kt < ntiles; kt++) {
        const float* kp = k + (size_t)(kt * 64 + r) * D + head * DH + c0;
        const float* vp = v + (size_t)(kt * 64 + r) * D + head * DH + c0;
#pragma unroll
        for (int j = 0; j < 8; j++) {
            ((float4*)&Ks[r][c0])[j] = ((const float4*)kp)[j];
            ((float4*)&Vs[r][c0])[j] = ((const float4*)vp)[j];
        }
        __syncthreads();

        int base = kt * 64;
        for (int cs = 0; cs < 64; cs += 4) {
            if (base + cs > qi) break;            // whole chunk masked -> done with tile
            float sv[4];
            float cmax = -INFINITY;
#pragma unroll
            for (int jj = 0; jj < 4; jj++) {
                const float4* kr = (const float4*)&Ks[cs + jj][0];
                float s0 = 0.f, s1 = 0.f, s2 = 0.f, s3 = 0.f;
#pragma unroll
                for (int i = 0; i < 16; i++) {
                    float4 kv = kr[i];
                    s0 += qr[4 * i + 0] * kv.x;
                    s1 += qr[4 * i + 1] * kv.y;
                    s2 += qr[4 * i + 2] * kv.z;
                    s3 += qr[4 * i + 3] * kv.w;
                }
                float s = (s0 + s1) + (s2 + s3);
                if (base + cs + jj > qi) s = -INFINITY;   // causal mask
                sv[jj] = s;
                cmax = fmaxf(cmax, s);
            }
            if (cmax > m) {                        // rare after warmup
                float alpha = __expf(m - cmax);    // exp(-inf)=0 handles first chunk
                l *= alpha;
#pragma unroll
                for (int d = 0; d < 64; d++) oa[d] *= alpha;
                m = cmax;
            }
#pragma unroll
            for (int jj = 0; jj < 4; jj++) {
                float p = __expf(sv[jj] - m);      // masked keys -> exp(-inf)=0
                l += p;
                const float4* vr = (const float4*)&Vs[cs + jj][0];
#pragma unroll
                for (int i = 0; i < 16; i++) {
                    float4 vv = vr[i];
                    oa[4 * i + 0] += p * vv.x;
                    oa[4 * i + 1] += p * vv.y;
                    oa[4 * i + 2] += p * vv.z;
                    oa[4 * i + 3] += p * vv.w;
                }
            }
        }
        __syncthreads();
    }

    float inv = 1.f / l;
    float* op = o + (size_t)qi * D + head * DH;
#pragma unroll
    for (int j = 0; j < 16; j++) {
        float4 t4;
        t4.x = oa[4 * j + 0] * inv;
        t4.y = oa[4 * j + 1] * inv;
        t4.z = oa[4 * j + 2] * inv;
        t4.w = oa[4 * j + 3] * inv;
        ((float4*)op)[j] = t4;
    }
}

// ---------------- out = x + b_mo + b_ao (GEMMs then accumulate on top) ----------------
__global__ void init_out_kernel(const float* __restrict__ x,
                                const float* __restrict__ bmo,
                                const float* __restrict__ bao,
                                float* __restrict__ out) {
    int i = blockIdx.x * blockDim.x + threadIdx.x;
    int col = i & (D - 1);
    out[i] = x[i] + bmo[col] + bao[col];
}

// ---------------- launch ----------------
extern "C" void kernel_launch(void* const* d_in, const int* in_sizes, int n_in,
                              void* d_out, int out_size) {
    const float* x        = (const float*)d_in[0];
    // d_in[1] = mask: causal tril, implemented analytically -> ignored
    const float* ln_scale = (const float*)d_in[2];
    const float* ln_bias  = (const float*)d_in[3];
    const float* w_in     = (const float*)d_in[4];
    const float* b_in     = (const float*)d_in[5];
    const float* wq       = (const float*)d_in[6];
    const float* bq       = (const float*)d_in[7];
    const float* wk       = (const float*)d_in[8];
    const float* bk       = (const float*)d_in[9];
    const float* wv       = (const float*)d_in[10];
    const float* bv       = (const float*)d_in[11];
    const float* qn       = (const float*)d_in[12];
    const float* kn       = (const float*)d_in[13];
    const float* w_mo     = (const float*)d_in[14];
    const float* b_mo     = (const float*)d_in[15];
    const float* w_ao     = (const float*)d_in[16];
    const float* b_ao     = (const float*)d_in[17];
    float* out = (float*)d_out;

    float *xn, *h, *q, *k, *v, *o;
    cudaGetSymbolAddress((void**)&xn, g_xn);
    cudaGetSymbolAddress((void**)&h,  g_h);
    cudaGetSymbolAddress((void**)&q,  g_q);
    cudaGetSymbolAddress((void**)&k,  g_k);
    cudaGetSymbolAddress((void**)&v,  g_v);
    cudaGetSymbolAddress((void**)&o,  g_o);

    // 1. PreNorm
    ln_kernel<<<S, 256>>>(x, ln_scale, ln_bias, xn);

    // 2. MLP input + GELU: h = gelu(xn @ w_in + b_in)
    sgemm_kernel<1><<<dim3(F / 128, S / 128), 256>>>(xn, w_in, b_in, h, S, F, D);

    // 3. QKV projections
    sgemm_kernel<0><<<dim3(D / 128, S / 128), 256>>>(xn, wq, bq, q, S, D, D);
    sgemm_kernel<0><<<dim3(D / 128, S / 128), 256>>>(xn, wk, bk, k, S, D, D);
    sgemm_kernel<0><<<dim3(D / 128, S / 128), 256>>>(xn, wv, bv, v, S, D, D);

    // 4. qk-norm (per-head LN, no bias)
    qknorm_kernel<<<(S * H) / 256, 256>>>(q, qn);
    qknorm_kernel<<<(S * H) / 256, 256>>>(k, kn);

    // 5. causal attention
    attn_kernel<<<dim3(S / 128, H), 128>>>(q, k, v, o);

    // 6. out = x + b_mo + b_ao, then += h@w_mo, += o@w_ao
    init_out_kernel<<<(S * D) / 256, 256>>>(x, b_mo, b_ao, out);
    sgemm_kernel<2><<<dim3(D / 128, S / 128), 256>>>(h, w_mo, nullptr, out, S, D, F);
    sgemm_kernel<2><<<dim3(D / 128, S / 128), 256>>>(o, w_ao, nullptr, out, S, D, D);
}

// round 5
// speedup vs baseline: 1.4119x; 1.4032x over previous
#include <cuda_runtime.h>
#include <cuda_bf16.h>
#include <math.h>
#include <stdint.h>

#define S 4096
#define D 1024
#define H 16
#define DH 64
#define F 4096
#define EPSF 1e-6f

// ---------------- scratch (device globals: alloc-free) ----------------
__device__ float g_xn[S * D];
__device__ float g_h [S * F];
__device__ float g_q [S * D];
__device__ float g_k [S * D];
__device__ float g_v [S * D];
__device__ float g_o [S * D];

// bf16 split planes (hi/lo) for activations
__device__ __nv_bfloat16 g_xnh[S * D], g_xnl[S * D];
__device__ __nv_bfloat16 g_hh [S * F], g_hl [S * F];
__device__ __nv_bfloat16 g_oh [S * D], g_ol [S * D];
// bf16 split planes for weights, TRANSPOSED to [N][K]
__device__ __nv_bfloat16 g_winh[F * D], g_winl[F * D];
__device__ __nv_bfloat16 g_wqh [D * D], g_wql [D * D];
__device__ __nv_bfloat16 g_wkh [D * D], g_wkl [D * D];
__device__ __nv_bfloat16 g_wvh [D * D], g_wvl [D * D];
__device__ __nv_bfloat16 g_wmoh[D * F], g_wmol[D * F];
__device__ __nv_bfloat16 g_waoh[D * D], g_waol[D * D];

// ---------------- small asm helpers (all base sm_103 instructions) ----------------
__device__ __forceinline__ uint32_t smem_u32(const void* p) {
    uint32_t a;
    asm("{ .reg .u64 t; cvta.to.shared.u64 t, %1; cvt.u32.u64 %0, t; }" : "=r"(a) : "l"(p));
    return a;
}
__device__ __forceinline__ void cp16(uint32_t d, const void* s) {
    asm volatile("cp.async.cg.shared.global [%0], [%1], 16;" :: "r"(d), "l"(s));
}
#define CP_COMMIT() asm volatile("cp.async.commit_group;" ::: "memory")
#define CP_WAIT1()  asm volatile("cp.async.wait_group 1;" ::: "memory")
#define CP_WAIT0()  asm volatile("cp.async.wait_group 0;" ::: "memory")

__device__ __forceinline__ void ldmx4(uint32_t* r, uint32_t a) {
    asm volatile("ldmatrix.sync.aligned.m8n8.x4.shared.b16 {%0,%1,%2,%3}, [%4];"
                 : "=r"(r[0]), "=r"(r[1]), "=r"(r[2]), "=r"(r[3]) : "r"(a));
}
__device__ __forceinline__ void ldmx2(uint32_t* r, uint32_t a) {
    asm volatile("ldmatrix.sync.aligned.m8n8.x2.shared.b16 {%0,%1}, [%2];"
                 : "=r"(r[0]), "=r"(r[1]) : "r"(a));
}
__device__ __forceinline__ void mma16816(float* c, const uint32_t* a, const uint32_t* b) {
    asm volatile("mma.sync.aligned.m16n8k16.row.col.f32.bf16.bf16.f32 "
                 "{%0,%1,%2,%3}, {%4,%5,%6,%7}, {%8,%9}, {%0,%1,%2,%3};"
                 : "+f"(c[0]), "+f"(c[1]), "+f"(c[2]), "+f"(c[3])
                 : "r"(a[0]), "r"(a[1]), "r"(a[2]), "r"(a[3]), "r"(b[0]), "r"(b[1]));
}

__device__ __forceinline__ float gelu_f(float x) {
    float x3 = x * x * x;
    return 0.5f * x * (1.f + tanhf(0.7978845608028654f * (x + 0.044715f * x3)));
}

// ---------------- split kernels: fp32 -> bf16 hi + bf16 lo ----------------
__global__ void split_kernel(const float* __restrict__ in,
                             __nv_bfloat16* __restrict__ hi,
                             __nv_bfloat16* __restrict__ lo) {
    int i = blockIdx.x * blockDim.x + threadIdx.x;
    float4 v = ((const float4*)in)[i];
    __nv_bfloat162 h0 = __floats2bfloat162_rn(v.x, v.y);
    __nv_bfloat162 h1 = __floats2bfloat162_rn(v.z, v.w);
    float r0 = v.x - __bfloat162float(__low2bfloat16(h0));
    float r1 = v.y - __bfloat162float(__high2bfloat16(h0));
    float r2 = v.z - __bfloat162float(__low2bfloat16(h1));
    float r3 = v.w - __bfloat162float(__high2bfloat16(h1));
    __nv_bfloat162 l0 = __floats2bfloat162_rn(r0, r1);
    __nv_bfloat162 l1 = __floats2bfloat162_rn(r2, r3);
    ((__nv_bfloat162*)hi)[2 * i]     = h0;
    ((__nv_bfloat162*)hi)[2 * i + 1] = h1;
    ((__nv_bfloat162*)lo)[2 * i]     = l0;
    ((__nv_bfloat162*)lo)[2 * i + 1] = l1;
}

// in [Kd][Nd] fp32 -> out [Nd][Kd] bf16 hi/lo (32x32 tiles). block (32,8)
__global__ void splitT_kernel(const float* __restrict__ in,
                              __nv_bfloat16* __restrict__ hi,
                              __nv_bfloat16* __restrict__ lo,
                              int Kd, int Nd) {
    __shared__ float t[32][33];
    int n0 = blockIdx.x * 32, k0 = blockIdx.y * 32;
    int tx = threadIdx.x, ty = threadIdx.y;
#pragma unroll
    for (int j = 0; j < 4; j++)
        t[ty + j * 8][tx] = in[(size_t)(k0 + ty + j * 8) * Nd + n0 + tx];
    __syncthreads();
#pragma unroll
    for (int j = 0; j < 4; j++) {
        float v = t[tx][ty + j * 8];                   // in[k0+tx][n0+ty+j*8]
        int n = n0 + ty + j * 8, k = k0 + tx;
        __nv_bfloat16 h = __float2bfloat16(v);
        hi[(size_t)n * Kd + k] = h;
        lo[(size_t)n * Kd + k] = __float2bfloat16(v - __bfloat162float(h));
    }
}

// ================= HMMA GEMM: C = epi(A[M,K] @ B^T[N,K]) =================
// A given as bf16 hi/lo planes [M][K]; B given as bf16 hi/lo planes [N][K].
// 3-term split: Ah*Bh + Ah*Bl + Al*Bh, fp32 accumulate in registers.
// MODE 0: C = acc + bias   MODE 1: C = gelu(acc + bias)   MODE 2: C += acc
#define GBM 128
#define GBN 128
#define GBK 32
#define PLANE_B (128 * 40 * 2)          // 10240 bytes per plane tile (80B row stride)
#define BUF_B   (4 * PLANE_B)           // Ah, Al, Bh, Bl
#define GSMEM   (2 * BUF_B)             // double buffered: 81920 bytes

__device__ __forceinline__ void issue_chunk(
    uint32_t base,
    const __nv_bfloat16* Ah, const __nv_bfloat16* Al,
    const __nv_bfloat16* Bh, const __nv_bfloat16* Bl,
    int bm, int bn, int kc, int K, int tid)
{
    int row  = tid >> 1;
    int half = tid & 1;
    uint32_t doff = row * 80 + half * 32;
    size_t aoff = (size_t)(bm + row) * K + kc + half * 16;
    size_t boff = (size_t)(bn + row) * K + kc + half * 16;
    cp16(base + doff,                    Ah + aoff);
    cp16(base + doff + 16,               Ah + aoff + 8);
    cp16(base + PLANE_B + doff,          Al + aoff);
    cp16(base + PLANE_B + doff + 16,     Al + aoff + 8);
    cp16(base + 2 * PLANE_B + doff,      Bh + boff);
    cp16(base + 2 * PLANE_B + doff + 16, Bh + boff + 8);
    cp16(base + 3 * PLANE_B + doff,      Bl + boff);
    cp16(base + 3 * PLANE_B + doff + 16, Bl + boff + 8);
}

template <int MODE>
__global__ void __launch_bounds__(256, 2) hmma_gemm(
    const __nv_bfloat16* __restrict__ Ah, const __nv_bfloat16* __restrict__ Al,
    const __nv_bfloat16* __restrict__ Bh, const __nv_bfloat16* __restrict__ Bl,
    const float* __restrict__ bias, float* __restrict__ C,
    int M, int N, int K)
{
    extern __shared__ __align__(128) char smem[];
    uint32_t sb = smem_u32(smem);
    int tid = threadIdx.x;
    int lane = tid & 31, wid = tid >> 5;
    int wm = wid >> 2, wn = wid & 3;          // warp grid 2 x 4 -> 64x32 warp tile
    int bm = blockIdx.y * GBM, bn = blockIdx.x * GBN;

    float acc[4][4][4];
#pragma unroll
    for (int i = 0; i < 4; i++)
#pragma unroll
        for (int j = 0; j < 4; j++)
#pragma unroll
            for (int r = 0; r < 4; r++) acc[i][j][r] = 0.f;

    // per-lane ldmatrix byte offsets (within a plane tile, 80B row stride)
    uint32_t a_off = (uint32_t)((wm * 64 + (lane & 7) + (lane & 8)) * 80 + ((lane >> 4) << 4));
    uint32_t b_off = (uint32_t)((wn * 32 + (lane & 7)) * 80 + ((lane & 8) << 1));

    int nk = K / GBK;
    issue_chunk(sb, Ah, Al, Bh, Bl, bm, bn, 0, K, tid);
    CP_COMMIT();

    for (int c = 0; c < nk; c++) {
        if (c + 1 < nk) {
            issue_chunk(sb + ((c + 1) & 1) * BUF_B, Ah, Al, Bh, Bl, bm, bn, (c + 1) * GBK, K, tid);
            CP_COMMIT();
            CP_WAIT1();
        } else {
            CP_WAIT0();
        }
        __syncthreads();

        uint32_t base = sb + (c & 1) * BUF_B;
        uint32_t aH = base, aL = base + PLANE_B;
        uint32_t bH = base + 2 * PLANE_B, bL = base + 3 * PLANE_B;

#pragma unroll
        for (int k16 = 0; k16 < 2; k16++) {
            uint32_t kb = k16 * 32;   // 16 bf16 = 32 bytes
            uint32_t ahf[4][4], bfr[4][2];
#pragma unroll
            for (int mt = 0; mt < 4; mt++) ldmx4(ahf[mt], aH + a_off + mt * 1280 + kb);
#pragma unroll
            for (int nt = 0; nt < 4; nt++) ldmx2(bfr[nt], bH + b_off + nt * 640 + kb);
#pragma unroll
            for (int mt = 0; mt < 4; mt++)
#pragma unroll
                for (int nt = 0; nt < 4; nt++) mma16816(acc[mt][nt], ahf[mt], bfr[nt]);

            uint32_t alf[4][4];
#pragma unroll
            for (int mt = 0; mt < 4; mt++) ldmx4(alf[mt], aL + a_off + mt * 1280 + kb);
#pragma unroll
            for (int mt = 0; mt < 4; mt++)
#pragma unroll
                for (int nt = 0; nt < 4; nt++) mma16816(acc[mt][nt], alf[mt], bfr[nt]);

#pragma unroll
            for (int nt = 0; nt < 4; nt++) ldmx2(bfr[nt], bL + b_off + nt * 640 + kb);
#pragma unroll
            for (int mt = 0; mt < 4; mt++)
#pragma unroll
                for (int nt = 0; nt < 4; nt++) mma16816(acc[mt][nt], ahf[mt], bfr[nt]);
        }
        __syncthreads();
    }

    // ---- epilogue ----
    int lr = lane >> 2, lc = (lane & 3) * 2;
#pragma unroll
    for (int mt = 0; mt < 4; mt++) {
#pragma unroll
        for (int nt = 0; nt < 4; nt++) {
            float* a = acc[mt][nt];
            int m0 = bm + wm * 64 + mt * 16 + lr;
            int n0 = bn + wn * 32 + nt * 8 + lc;
            float2* p0 = (float2*)(C + (size_t)m0 * N + n0);
            float2* p1 = (float2*)(C + (size_t)(m0 + 8) * N + n0);
            if (MODE == 2) {
                float2 v0 = *p0, v1 = *p1;
                v0.x += a[0]; v0.y += a[1];
                v1.x += a[2]; v1.y += a[3];
                *p0 = v0; *p1 = v1;
            } else {
                float b0 = bias[n0], b1 = bias[n0 + 1];
                float v0 = a[0] + b0, v1 = a[1] + b1;
                float v2 = a[2] + b0, v3 = a[3] + b1;
                if (MODE == 1) {
                    v0 = gelu_f(v0); v1 = gelu_f(v1);
                    v2 = gelu_f(v2); v3 = gelu_f(v3);
                }
                float2 w0 = {v0, v1}, w1 = {v2, v3};
                *p0 = w0; *p1 = w1;
            }
        }
    }
}

// ---------------- LayerNorm over D=1024, block per row ----------------
__global__ void ln_kernel(const float* __restrict__ x,
                          const float* __restrict__ gamma,
                          const float* __restrict__ beta,
                          float* __restrict__ y) {
    __shared__ float sh[8];
    __shared__ float stat;
    int row = blockIdx.x;
    int t = threadIdx.x;
    const float4* xr = (const float4*)(x + (size_t)row * D);
    float4 xv = xr[t];

    float s = xv.x + xv.y + xv.z + xv.w;
#pragma unroll
    for (int o = 16; o > 0; o >>= 1) s += __shfl_xor_sync(0xffffffffu, s, o);
    if ((t & 31) == 0) sh[t >> 5] = s;
    __syncthreads();
    if (t == 0) {
        float tot = 0.f;
#pragma unroll
        for (int i = 0; i < 8; i++) tot += sh[i];
        stat = tot * (1.f / (float)D);
    }
    __syncthreads();
    float mean = stat;

    float d0 = xv.x - mean, d1 = xv.y - mean, d2 = xv.z - mean, d3 = xv.w - mean;
    float sq = d0 * d0 + d1 * d1 + d2 * d2 + d3 * d3;
#pragma unroll
    for (int o = 16; o > 0; o >>= 1) sq += __shfl_xor_sync(0xffffffffu, sq, o);
    __syncthreads();
    if ((t & 31) == 0) sh[t >> 5] = sq;
    __syncthreads();
    if (t == 0) {
        float tot = 0.f;
#pragma unroll
        for (int i = 0; i < 8; i++) tot += sh[i];
        stat = rsqrtf(tot * (1.f / (float)D) + EPSF);
    }
    __syncthreads();
    float rinv = stat;

    float4 gv = ((const float4*)gamma)[t];
    float4 bv = ((const float4*)beta)[t];
    float4 o4;
    o4.x = d0 * rinv * gv.x + bv.x;
    o4.y = d1 * rinv * gv.y + bv.y;
    o4.z = d2 * rinv * gv.z + bv.z;
    o4.w = d3 * rinv * gv.w + bv.w;
    ((float4*)(y + (size_t)row * D))[t] = o4;
}

// ---------------- per-head LN (Dh=64, no bias), thread per row ----------------
__global__ void qknorm_kernel(float* __restrict__ tq, const float* __restrict__ scale) {
    int row = blockIdx.x * blockDim.x + threadIdx.x;
    float* p = tq + (size_t)row * DH;
    float4 v[16];
    float s = 0.f;
#pragma unroll
    for (int i = 0; i < 16; i++) {
        v[i] = ((const float4*)p)[i];
        s += v[i].x + v[i].y + v[i].z + v[i].w;
    }
    float mean = s * (1.f / (float)DH);
    float sq = 0.f;
#pragma unroll
    for (int i = 0; i < 16; i++) {
        v[i].x -= mean; v[i].y -= mean; v[i].z -= mean; v[i].w -= mean;
        sq += v[i].x * v[i].x + v[i].y * v[i].y + v[i].z * v[i].z + v[i].w * v[i].w;
    }
    float r = rsqrtf(sq * (1.f / (float)DH) + EPSF);
#pragma unroll
    for (int i = 0; i < 16; i++) {
        float4 sc = ((const float4*)scale)[i];
        float4 o4;
        o4.x = v[i].x * r * sc.x;
        o4.y = v[i].y * r * sc.y;
        o4.z = v[i].z * r * sc.z;
        o4.w = v[i].w * r * sc.w;
        ((float4*)p)[i] = o4;
    }
}

// ---------------- causal flash attention, thread per (head, query) ----------------
__global__ void __launch_bounds__(128) attn_kernel(
    const float* __restrict__ q, const float* __restrict__ k,
    const float* __restrict__ v, float* __restrict__ o)
{
    __shared__ float Ks[64][64];
    __shared__ float Vs[64][64];
    int head = blockIdx.y;
    int qi = blockIdx.x * 128 + threadIdx.x;

    float qr[64];
    const float* qp = q + (size_t)qi * D + head * DH;
#pragma unroll
    for (int j = 0; j < 16; j++) {
        float4 t4 = ((const float4*)qp)[j];
        qr[4 * j + 0] = t4.x * 0.125f;
        qr[4 * j + 1] = t4.y * 0.125f;
        qr[4 * j + 2] = t4.z * 0.125f;
        qr[4 * j + 3] = t4.w * 0.125f;
    }

    float oa[64];
#pragma unroll
    for (int d = 0; d < 64; d++) oa[d] = 0.f;
    float m = -INFINITY, l = 0.f;

    int ntiles = blockIdx.x * 2 + 2;
    int r = threadIdx.x >> 1;
    int c0 = (threadIdx.x & 1) * 32;

    for (int kt = 0; kt < ntiles; kt++) {
        const float* kp = k + (size_t)(kt * 64 + r) * D + head * DH + c0;
        const float* vp = v + (size_t)(kt * 64 + r) * D + head * DH + c0;
#pragma unroll
        for (int j = 0; j < 8; j++) {
            ((float4*)&Ks[r][c0])[j] = ((const float4*)kp)[j];
            ((float4*)&Vs[r][c0])[j] = ((const float4*)vp)[j];
        }
        __syncthreads();

        int base = kt * 64;
        for (int cs = 0; cs < 64; cs += 4) {
            if (base + cs > qi) break;
            float sv[4];
            float cmax = -INFINITY;
#pragma unroll
            for (int jj = 0; jj < 4; jj++) {
                const float4* kr = (const float4*)&Ks[cs + jj][0];
                float s0 = 0.f, s1 = 0.f, s2 = 0.f, s3 = 0.f;
#pragma unroll
                for (int i = 0; i < 16; i++) {
                    float4 kv = kr[i];
                    s0 += qr[4 * i + 0] * kv.x;
                    s1 += qr[4 * i + 1] * kv.y;
                    s2 += qr[4 * i + 2] * kv.z;
                    s3 += qr[4 * i + 3] * kv.w;
                }
                float s = (s0 + s1) + (s2 + s3);
                if (base + cs + jj > qi) s = -INFINITY;
                sv[jj] = s;
                cmax = fmaxf(cmax, s);
            }
            if (cmax > m) {
                float alpha = __expf(m - cmax);
                l *= alpha;
#pragma unroll
                for (int d = 0; d < 64; d++) oa[d] *= alpha;
                m = cmax;
            }
#pragma unroll
            for (int jj = 0; jj < 4; jj++) {
                float p = __expf(sv[jj] - m);
                l += p;
                const float4* vr = (const float4*)&Vs[cs + jj][0];
#pragma unroll
                for (int i = 0; i < 16; i++) {
                    float4 vv = vr[i];
                    oa[4 * i + 0] += p * vv.x;
                    oa[4 * i + 1] += p * vv.y;
                    oa[4 * i + 2] += p * vv.z;
                    oa[4 * i + 3] += p * vv.w;
                }
            }
        }
        __syncthreads();
    }

    float inv = 1.f / l;
    float* op = o + (size_t)qi * D + head * DH;
#pragma unroll
    for (int j = 0; j < 16; j++) {
        float4 t4;
        t4.x = oa[4 * j + 0] * inv;
        t4.y = oa[4 * j + 1] * inv;
        t4.z = oa[4 * j + 2] * inv;
        t4.w = oa[4 * j + 3] * inv;
        ((float4*)op)[j] = t4;
    }
}

// ---------------- out = x + b_mo + b_ao ----------------
__global__ void init_out_kernel(const float* __restrict__ x,
                                const float* __restrict__ bmo,
                                const float* __restrict__ bao,
                                float* __restrict__ out) {
    int i = blockIdx.x * blockDim.x + threadIdx.x;
    int col = i & (D - 1);
    out[i] = x[i] + bmo[col] + bao[col];
}

// ---------------- launch ----------------
extern "C" void kernel_launch(void* const* d_in, const int* in_sizes, int n_in,
                              void* d_out, int out_size) {
    const float* x        = (const float*)d_in[0];
    // d_in[1] = mask (causal tril) handled analytically
    const float* ln_scale = (const float*)d_in[2];
    const float* ln_bias  = (const float*)d_in[3];
    const float* w_in     = (const float*)d_in[4];
    const float* b_in     = (const float*)d_in[5];
    const float* wq       = (const float*)d_in[6];
    const float* bq       = (const float*)d_in[7];
    const float* wk       = (const float*)d_in[8];
    const float* bk       = (const float*)d_in[9];
    const float* wv       = (const float*)d_in[10];
    const float* bv       = (const float*)d_in[11];
    const float* qn       = (const float*)d_in[12];
    const float* kn       = (const float*)d_in[13];
    const float* w_mo     = (const float*)d_in[14];
    const float* b_mo     = (const float*)d_in[15];
    const float* w_ao     = (const float*)d_in[16];
    const float* b_ao     = (const float*)d_in[17];
    float* out = (float*)d_out;

    float *xn, *h, *q, *k, *v, *o;
    cudaGetSymbolAddress((void**)&xn, g_xn);
    cudaGetSymbolAddress((void**)&h,  g_h);
    cudaGetSymbolAddress((void**)&q,  g_q);
    cudaGetSymbolAddress((void**)&k,  g_k);
    cudaGetSymbolAddress((void**)&v,  g_v);
    cudaGetSymbolAddress((void**)&o,  g_o);

    __nv_bfloat16 *xnh, *xnl, *hh, *hl, *oh, *ol;
    __nv_bfloat16 *winh, *winl, *wqh, *wql, *wkh, *wkl, *wvh, *wvl, *wmoh, *wmol, *waoh, *waol;
    cudaGetSymbolAddress((void**)&xnh, g_xnh);  cudaGetSymbolAddress((void**)&xnl, g_xnl);
    cudaGetSymbolAddress((void**)&hh,  g_hh);   cudaGetSymbolAddress((void**)&hl,  g_hl);
    cudaGetSymbolAddress((void**)&oh,  g_oh);   cudaGetSymbolAddress((void**)&ol,  g_ol);
    cudaGetSymbolAddress((void**)&winh, g_winh); cudaGetSymbolAddress((void**)&winl, g_winl);
    cudaGetSymbolAddress((void**)&wqh, g_wqh);  cudaGetSymbolAddress((void**)&wql, g_wql);
    cudaGetSymbolAddress((void**)&wkh, g_wkh);  cudaGetSymbolAddress((void**)&wkl, g_wkl);
    cudaGetSymbolAddress((void**)&wvh, g_wvh);  cudaGetSymbolAddress((void**)&wvl, g_wvl);
    cudaGetSymbolAddress((void**)&wmoh, g_wmoh); cudaGetSymbolAddress((void**)&wmol, g_wmol);
    cudaGetSymbolAddress((void**)&waoh, g_waoh); cudaGetSymbolAddress((void**)&waol, g_waol);

    cudaFuncSetAttribute(hmma_gemm<0>, cudaFuncAttributeMaxDynamicSharedMemorySize, GSMEM);
    cudaFuncSetAttribute(hmma_gemm<1>, cudaFuncAttributeMaxDynamicSharedMemorySize, GSMEM);
    cudaFuncSetAttribute(hmma_gemm<2>, cudaFuncAttributeMaxDynamicSharedMemorySize, GSMEM);

    // weight split+transpose ([K][N] -> [N][K] bf16 hi/lo)
    splitT_kernel<<<dim3(F / 32, D / 32), dim3(32, 8)>>>(w_in, winh, winl, D, F);
    splitT_kernel<<<dim3(D / 32, D / 32), dim3(32, 8)>>>(wq, wqh, wql, D, D);
    splitT_kernel<<<dim3(D / 32, D / 32), dim3(32, 8)>>>(wk, wkh, wkl, D, D);
    splitT_kernel<<<dim3(D / 32, D / 32), dim3(32, 8)>>>(wv, wvh, wvl, D, D);
    splitT_kernel<<<dim3(D / 32, F / 32), dim3(32, 8)>>>(w_mo, wmoh, wmol, F, D);
    splitT_kernel<<<dim3(D / 32, D / 32), dim3(32, 8)>>>(w_ao, waoh, waol, D, D);

    // 1. PreNorm + split
    ln_kernel<<<S, 256>>>(x, ln_scale, ln_bias, xn);
    split_kernel<<<(S * D / 4) / 256, 256>>>(xn, xnh, xnl);

    // 2. MLP input + GELU: h = gelu(xn @ w_in + b_in)
    hmma_gemm<1><<<dim3(F / 128, S / 128), 256, GSMEM>>>(xnh, xnl, winh, winl, b_in, h, S, F, D);
    split_kernel<<<(S * F / 4) / 256, 256>>>(h, hh, hl);

    // 3. QKV projections
    hmma_gemm<0><<<dim3(D / 128, S / 128), 256, GSMEM>>>(xnh, xnl, wqh, wql, bq, q, S, D, D);
    hmma_gemm<0><<<dim3(D / 128, S / 128), 256, GSMEM>>>(xnh, xnl, wkh, wkl, bk, k, S, D, D);
    hmma_gemm<0><<<dim3(D / 128, S / 128), 256, GSMEM>>>(xnh, xnl, wvh, wvl, bv, v, S, D, D);

    // 4. qk-norm
    qknorm_kernel<<<(S * H) / 256, 256>>>(q, qn);
    qknorm_kernel<<<(S * H) / 256, 256>>>(k, kn);

    // 5. causal attention + split o
    attn_kernel<<<dim3(S / 128, H), 128>>>(q, k, v, o);
    split_kernel<<<(S * D / 4) / 256, 256>>>(o, oh, ol);

    // 6. out = x + b_mo + b_ao, then += h@w_mo, += o@w_ao
    init_out_kernel<<<(S * D) / 256, 256>>>(x, b_mo, b_ao, out);
    hmma_gemm<2><<<dim3(D / 128, S / 128), 256, GSMEM>>>(hh, hl, wmoh, wmol, nullptr, out, S, D, F);
    hmma_gemm<2><<<dim3(D / 128, S / 128), 256, GSMEM>>>(oh, ol, waoh, waol, nullptr, out, S, D, D);
}

// round 6
// speedup vs baseline: 2.8889x; 2.0461x over previous
#include <cuda_runtime.h>
#include <cuda_bf16.h>
#include <math.h>
#include <stdint.h>

#define S 4096
#define D 1024
#define H 16
#define DH 64
#define F 4096
#define EPSF 1e-6f

// ---------------- scratch (device globals: alloc-free) ----------------
__device__ float g_xn[S * D];
__device__ float g_h [S * F];
__device__ float g_q [S * D];
__device__ float g_k [S * D];
__device__ float g_v [S * D];
__device__ float g_o [S * D];

// bf16 split planes (hi/lo) for activations
__device__ __nv_bfloat16 g_xnh[S * D], g_xnl[S * D];
__device__ __nv_bfloat16 g_hh [S * F], g_hl [S * F];
__device__ __nv_bfloat16 g_oh [S * D], g_ol [S * D];
// attention operand planes
__device__ __nv_bfloat16 g_qsh[S * D], g_qsl[S * D];   // q * 1/8, hi/lo
__device__ __nv_bfloat16 g_ksh[S * D], g_ksl[S * D];   // k hi/lo
__device__ __nv_bfloat16 g_vth[D * S], g_vtl[D * S];   // V^T per head: [H*64 dims][S keys]
// bf16 split planes for weights, TRANSPOSED to [N][K]
__device__ __nv_bfloat16 g_winh[F * D], g_winl[F * D];
__device__ __nv_bfloat16 g_wqh [D * D], g_wql [D * D];
__device__ __nv_bfloat16 g_wkh [D * D], g_wkl [D * D];
__device__ __nv_bfloat16 g_wvh [D * D], g_wvl [D * D];
__device__ __nv_bfloat16 g_wmoh[D * F], g_wmol[D * F];
__device__ __nv_bfloat16 g_waoh[D * D], g_waol[D * D];

// ---------------- small asm helpers (all base sm_103 instructions) ----------------
__device__ __forceinline__ uint32_t smem_u32(const void* p) {
    uint32_t a;
    asm("{ .reg .u64 t; cvta.to.shared.u64 t, %1; cvt.u32.u64 %0, t; }" : "=r"(a) : "l"(p));
    return a;
}
__device__ __forceinline__ void cp16(uint32_t d, const void* s) {
    asm volatile("cp.async.cg.shared.global [%0], [%1], 16;" :: "r"(d), "l"(s));
}
#define CP_COMMIT() asm volatile("cp.async.commit_group;" ::: "memory")
#define CP_WAIT1()  asm volatile("cp.async.wait_group 1;" ::: "memory")
#define CP_WAIT0()  asm volatile("cp.async.wait_group 0;" ::: "memory")

__device__ __forceinline__ void ldmx4(uint32_t* r, uint32_t a) {
    asm volatile("ldmatrix.sync.aligned.m8n8.x4.shared.b16 {%0,%1,%2,%3}, [%4];"
                 : "=r"(r[0]), "=r"(r[1]), "=r"(r[2]), "=r"(r[3]) : "r"(a));
}
__device__ __forceinline__ void ldmx2(uint32_t* r, uint32_t a) {
    asm volatile("ldmatrix.sync.aligned.m8n8.x2.shared.b16 {%0,%1}, [%2];"
                 : "=r"(r[0]), "=r"(r[1]) : "r"(a));
}
__device__ __forceinline__ void mma16816(float* c, const uint32_t* a, const uint32_t* b) {
    asm volatile("mma.sync.aligned.m16n8k16.row.col.f32.bf16.bf16.f32 "
                 "{%0,%1,%2,%3}, {%4,%5,%6,%7}, {%8,%9}, {%0,%1,%2,%3};"
                 : "+f"(c[0]), "+f"(c[1]), "+f"(c[2]), "+f"(c[3])
                 : "r"(a[0]), "r"(a[1]), "r"(a[2]), "r"(a[3]), "r"(b[0]), "r"(b[1]));
}

__device__ __forceinline__ float gelu_f(float x) {
    float x3 = x * x * x;
    return 0.5f * x * (1.f + tanhf(0.7978845608028654f * (x + 0.044715f * x3)));
}

__device__ __forceinline__ void packsplit(uint32_t& hi, uint32_t& lo, float a, float b) {
    __nv_bfloat162 h = __floats2bfloat162_rn(a, b);
    float r0 = a - __bfloat162float(__low2bfloat16(h));
    float r1 = b - __bfloat162float(__high2bfloat16(h));
    __nv_bfloat162 l = __floats2bfloat162_rn(r0, r1);
    hi = *reinterpret_cast<uint32_t*>(&h);
    lo = *reinterpret_cast<uint32_t*>(&l);
}

// ---------------- split kernels: fp32 -> bf16 hi + bf16 lo ----------------
__global__ void split_kernel(const float* __restrict__ in,
                             __nv_bfloat16* __restrict__ hi,
                             __nv_bfloat16* __restrict__ lo,
                             float scale) {
    int i = blockIdx.x * blockDim.x + threadIdx.x;
    float4 v = ((const float4*)in)[i];
    v.x *= scale; v.y *= scale; v.z *= scale; v.w *= scale;
    uint32_t h0, l0, h1, l1;
    packsplit(h0, l0, v.x, v.y);
    packsplit(h1, l1, v.z, v.w);
    ((uint32_t*)hi)[2 * i]     = h0;
    ((uint32_t*)hi)[2 * i + 1] = h1;
    ((uint32_t*)lo)[2 * i]     = l0;
    ((uint32_t*)lo)[2 * i + 1] = l1;
}

// in [Kd][Nd] fp32 -> out [Nd][Kd] bf16 hi/lo (32x32 tiles). block (32,8)
__global__ void splitT_kernel(const float* __restrict__ in,
                              __nv_bfloat16* __restrict__ hi,
                              __nv_bfloat16* __restrict__ lo,
                              int Kd, int Nd) {
    __shared__ float t[32][33];
    int n0 = blockIdx.x * 32, k0 = blockIdx.y * 32;
    int tx = threadIdx.x, ty = threadIdx.y;
#pragma unroll
    for (int j = 0; j < 4; j++)
        t[ty + j * 8][tx] = in[(size_t)(k0 + ty + j * 8) * Nd + n0 + tx];
    __syncthreads();
#pragma unroll
    for (int j = 0; j < 4; j++) {
        float v = t[tx][ty + j * 8];
        int n = n0 + ty + j * 8, k = k0 + tx;
        __nv_bfloat16 h = __float2bfloat16(v);
        hi[(size_t)n * Kd + k] = h;
        lo[(size_t)n * Kd + k] = __float2bfloat16(v - __bfloat162float(h));
    }
}

// ================= HMMA GEMM: C = epi(A[M,K] @ B^T[N,K]) =================
#define GBM 128
#define GBN 128
#define GBK 32
#define PLANE_B (128 * 40 * 2)
#define BUF_B   (4 * PLANE_B)
#define GSMEM   (2 * BUF_B)

__device__ __forceinline__ void issue_chunk(
    uint32_t base,
    const __nv_bfloat16* Ah, const __nv_bfloat16* Al,
    const __nv_bfloat16* Bh, const __nv_bfloat16* Bl,
    int bm, int bn, int kc, int K, int tid)
{
    int row  = tid >> 1;
    int half = tid & 1;
    uint32_t doff = row * 80 + half * 32;
    size_t aoff = (size_t)(bm + row) * K + kc + half * 16;
    size_t boff = (size_t)(bn + row) * K + kc + half * 16;
    cp16(base + doff,                    Ah + aoff);
    cp16(base + doff + 16,               Ah + aoff + 8);
    cp16(base + PLANE_B + doff,          Al + aoff);
    cp16(base + PLANE_B + doff + 16,     Al + aoff + 8);
    cp16(base + 2 * PLANE_B + doff,      Bh + boff);
    cp16(base + 2 * PLANE_B + doff + 16, Bh + boff + 8);
    cp16(base + 3 * PLANE_B + doff,      Bl + boff);
    cp16(base + 3 * PLANE_B + doff + 16, Bl + boff + 8);
}

template <int MODE>
__global__ void __launch_bounds__(256, 2) hmma_gemm(
    const __nv_bfloat16* __restrict__ Ah, const __nv_bfloat16* __restrict__ Al,
    const __nv_bfloat16* __restrict__ Bh, const __nv_bfloat16* __restrict__ Bl,
    const float* __restrict__ bias, float* __restrict__ C,
    int M, int N, int K)
{
    extern __shared__ __align__(128) char smem[];
    uint32_t sb = smem_u32(smem);
    int tid = threadIdx.x;
    int lane = tid & 31, wid = tid >> 5;
    int wm = wid >> 2, wn = wid & 3;
    int bm = blockIdx.y * GBM, bn = blockIdx.x * GBN;

    float acc[4][4][4];
#pragma unroll
    for (int i = 0; i < 4; i++)
#pragma unroll
        for (int j = 0; j < 4; j++)
#pragma unroll
            for (int r = 0; r < 4; r++) acc[i][j][r] = 0.f;

    uint32_t a_off = (uint32_t)((wm * 64 + (lane & 7) + (lane & 8)) * 80 + ((lane >> 4) << 4));
    uint32_t b_off = (uint32_t)((wn * 32 + (lane & 7)) * 80 + ((lane & 8) << 1));

    int nk = K / GBK;
    issue_chunk(sb, Ah, Al, Bh, Bl, bm, bn, 0, K, tid);
    CP_COMMIT();

    for (int c = 0; c < nk; c++) {
        if (c + 1 < nk) {
            issue_chunk(sb + ((c + 1) & 1) * BUF_B, Ah, Al, Bh, Bl, bm, bn, (c + 1) * GBK, K, tid);
            CP_COMMIT();
            CP_WAIT1();
        } else {
            CP_WAIT0();
        }
        __syncthreads();

        uint32_t base = sb + (c & 1) * BUF_B;
        uint32_t aH = base, aL = base + PLANE_B;
        uint32_t bH = base + 2 * PLANE_B, bL = base + 3 * PLANE_B;

#pragma unroll
        for (int k16 = 0; k16 < 2; k16++) {
            uint32_t kb = k16 * 32;
            uint32_t ahf[4][4], bfr[4][2];
#pragma unroll
            for (int mt = 0; mt < 4; mt++) ldmx4(ahf[mt], aH + a_off + mt * 1280 + kb);
#pragma unroll
            for (int nt = 0; nt < 4; nt++) ldmx2(bfr[nt], bH + b_off + nt * 640 + kb);
#pragma unroll
            for (int mt = 0; mt < 4; mt++)
#pragma unroll
                for (int nt = 0; nt < 4; nt++) mma16816(acc[mt][nt], ahf[mt], bfr[nt]);

            uint32_t alf[4][4];
#pragma unroll
            for (int mt = 0; mt < 4; mt++) ldmx4(alf[mt], aL + a_off + mt * 1280 + kb);
#pragma unroll
            for (int mt = 0; mt < 4; mt++)
#pragma unroll
                for (int nt = 0; nt < 4; nt++) mma16816(acc[mt][nt], alf[mt], bfr[nt]);

#pragma unroll
            for (int nt = 0; nt < 4; nt++) ldmx2(bfr[nt], bL + b_off + nt * 640 + kb);
#pragma unroll
            for (int mt = 0; mt < 4; mt++)
#pragma unroll
                for (int nt = 0; nt < 4; nt++) mma16816(acc[mt][nt], ahf[mt], bfr[nt]);
        }
        __syncthreads();
    }

    int lr = lane >> 2, lc = (lane & 3) * 2;
#pragma unroll
    for (int mt = 0; mt < 4; mt++) {
#pragma unroll
        for (int nt = 0; nt < 4; nt++) {
            float* a = acc[mt][nt];
            int m0 = bm + wm * 64 + mt * 16 + lr;
            int n0 = bn + wn * 32 + nt * 8 + lc;
            float2* p0 = (float2*)(C + (size_t)m0 * N + n0);
            float2* p1 = (float2*)(C + (size_t)(m0 + 8) * N + n0);
            if (MODE == 2) {
                float2 v0 = *p0, v1 = *p1;
                v0.x += a[0]; v0.y += a[1];
                v1.x += a[2]; v1.y += a[3];
                *p0 = v0; *p1 = v1;
            } else {
                float b0 = bias[n0], b1 = bias[n0 + 1];
                float v0 = a[0] + b0, v1 = a[1] + b1;
                float v2 = a[2] + b0, v3 = a[3] + b1;
                if (MODE == 1) {
                    v0 = gelu_f(v0); v1 = gelu_f(v1);
                    v2 = gelu_f(v2); v3 = gelu_f(v3);
                }
                float2 w0 = {v0, v1}, w1 = {v2, v3};
                *p0 = w0; *p1 = w1;
            }
        }
    }
}

// ================= HMMA flash attention =================
// per CTA: 128 queries x 1 head; 8 warps x 16 rows; K/V tiles of 64 keys.
#define AT_STRIDE 144
#define AT_PLANE (64 * AT_STRIDE)     // 9216 B
#define AT_BUF   (4 * AT_PLANE)       // kh, kl, vth, vtl
#define AT_SMEM  (2 * AT_BUF)         // 73728 B

__device__ __forceinline__ void at_load_tile(
    uint32_t dst, const __nv_bfloat16* kh, const __nv_bfloat16* kl,
    const __nv_bfloat16* vth, const __nv_bfloat16* vtl,
    int head, int kt, int tid)
{
    int row = tid >> 2, q4 = tid & 3;
    size_t koff = (size_t)(kt * 64 + row) * D + head * DH + q4 * 16;
    uint32_t d = dst + row * AT_STRIDE + q4 * 32;
    cp16(d,                    kh + koff);
    cp16(d + 16,               kh + koff + 8);
    cp16(d + AT_PLANE,         kl + koff);
    cp16(d + AT_PLANE + 16,    kl + koff + 8);
    size_t voff = (size_t)(head * DH + row) * S + kt * 64 + q4 * 16;
    cp16(d + 2 * AT_PLANE,      vth + voff);
    cp16(d + 2 * AT_PLANE + 16, vth + voff + 8);
    cp16(d + 3 * AT_PLANE,      vtl + voff);
    cp16(d + 3 * AT_PLANE + 16, vtl + voff + 8);
}

__global__ void __launch_bounds__(256, 1) hmma_attn(
    const __nv_bfloat16* __restrict__ qh, const __nv_bfloat16* __restrict__ ql,
    const __nv_bfloat16* __restrict__ kh, const __nv_bfloat16* __restrict__ kl,
    const __nv_bfloat16* __restrict__ vth, const __nv_bfloat16* __restrict__ vtl,
    float* __restrict__ o)
{
    extern __shared__ __align__(128) char smem[];
    uint32_t sb = smem_u32(smem);
    int tid = threadIdx.x, lane = tid & 31, wid = tid >> 5;
    int qt = (int)gridDim.x - 1 - (int)blockIdx.x;   // heavy tiles first
    int head = blockIdx.y;
    int ntiles = 2 * qt + 2;

    // Q tile (128x64, hi/lo) staged through buf1 region
    {
        int row = tid >> 1, half = tid & 1;
        const __nv_bfloat16* s0 = qh + (size_t)(qt * 128 + row) * D + head * DH + half * 32;
        const __nv_bfloat16* s1 = ql + (size_t)(qt * 128 + row) * D + head * DH + half * 32;
        uint32_t dq = sb + AT_BUF + row * AT_STRIDE + half * 64;
        cp16(dq,      s0); cp16(dq + 16, s0 + 8);
        cp16(dq + 32, s0 + 16); cp16(dq + 48, s0 + 24);
        uint32_t dl = dq + 2 * AT_PLANE;
        cp16(dl,      s1); cp16(dl + 16, s1 + 8);
        cp16(dl + 32, s1 + 16); cp16(dl + 48, s1 + 24);
    }
    CP_COMMIT();
    at_load_tile(sb, kh, kl, vth, vtl, head, 0, tid);
    CP_COMMIT();
    CP_WAIT0();
    __syncthreads();

    uint32_t qhf[4][4], qlf[4][4];
#pragma unroll
    for (int kc = 0; kc < 4; kc++) {
        uint32_t a = sb + AT_BUF + (wid * 16 + (lane & 15)) * AT_STRIDE
                   + ((lane >> 4) & 1) * 16 + kc * 32;
        ldmx4(qhf[kc], a);
        ldmx4(qlf[kc], a + 2 * AT_PLANE);
    }
    __syncthreads();
    if (ntiles > 1) { at_load_tile(sb + AT_BUF, kh, kl, vth, vtl, head, 1, tid); CP_COMMIT(); }

    float oacc[8][4];
#pragma unroll
    for (int i = 0; i < 8; i++)
#pragma unroll
        for (int j = 0; j < 4; j++) oacc[i][j] = 0.f;
    float m0 = -INFINITY, m1 = -INFINITY, l0 = 0.f, l1 = 0.f;
    int row0 = qt * 128 + wid * 16 + (lane >> 2);

    for (int kt = 0; kt < ntiles; kt++) {
        if (kt + 1 < ntiles) CP_WAIT1(); else CP_WAIT0();
        __syncthreads();
        uint32_t base = sb + (kt & 1) * AT_BUF;

        if (kt * 64 <= qt * 128 + wid * 16 + 15) {   // warp has unmasked keys in this tile
            float s[8][4];
#pragma unroll
            for (int i = 0; i < 8; i++)
#pragma unroll
                for (int j = 0; j < 4; j++) s[i][j] = 0.f;

            // S = Q @ K^T (3-term bf16 split)
#pragma unroll
            for (int kc = 0; kc < 4; kc++) {
                uint32_t koff = ((lane & 8) << 1) + kc * 32;
#pragma unroll
                for (int nt = 0; nt < 8; nt++) {
                    uint32_t ka = base + (nt * 8 + (lane & 7)) * AT_STRIDE + koff;
                    uint32_t bh[2], bl[2];
                    ldmx2(bh, ka);
                    ldmx2(bl, ka + AT_PLANE);
                    mma16816(s[nt], qhf[kc], bh);
                    mma16816(s[nt], qhf[kc], bl);
                    mma16816(s[nt], qlf[kc], bh);
                }
            }

            // causal mask (diagonal tiles only)
            if (kt >= 2 * qt) {
#pragma unroll
                for (int nt = 0; nt < 8; nt++) {
                    int c = kt * 64 + nt * 8 + 2 * (lane & 3);
                    if (c     > row0)     s[nt][0] = -INFINITY;
                    if (c + 1 > row0)     s[nt][1] = -INFINITY;
                    if (c     > row0 + 8) s[nt][2] = -INFINITY;
                    if (c + 1 > row0 + 8) s[nt][3] = -INFINITY;
                }
            }

            // online softmax
            float mx0 = -INFINITY, mx1 = -INFINITY;
#pragma unroll
            for (int nt = 0; nt < 8; nt++) {
                mx0 = fmaxf(mx0, fmaxf(s[nt][0], s[nt][1]));
                mx1 = fmaxf(mx1, fmaxf(s[nt][2], s[nt][3]));
            }
            mx0 = fmaxf(mx0, __shfl_xor_sync(0xffffffffu, mx0, 1));
            mx0 = fmaxf(mx0, __shfl_xor_sync(0xffffffffu, mx0, 2));
            mx1 = fmaxf(mx1, __shfl_xor_sync(0xffffffffu, mx1, 1));
            mx1 = fmaxf(mx1, __shfl_xor_sync(0xffffffffu, mx1, 2));
            float nm0 = fmaxf(m0, mx0), nm1 = fmaxf(m1, mx1);
            float a0 = __expf(m0 - nm0), a1 = __expf(m1 - nm1);
            m0 = nm0; m1 = nm1;
            float ps0 = 0.f, ps1 = 0.f;
#pragma unroll
            for (int nt = 0; nt < 8; nt++) {
                s[nt][0] = __expf(s[nt][0] - m0); ps0 += s[nt][0];
                s[nt][1] = __expf(s[nt][1] - m0); ps0 += s[nt][1];
                s[nt][2] = __expf(s[nt][2] - m1); ps1 += s[nt][2];
                s[nt][3] = __expf(s[nt][3] - m1); ps1 += s[nt][3];
            }
            l0 = l0 * a0 + ps0;
            l1 = l1 * a1 + ps1;
#pragma unroll
            for (int dt = 0; dt < 8; dt++) {
                oacc[dt][0] *= a0; oacc[dt][1] *= a0;
                oacc[dt][2] *= a1; oacc[dt][3] *= a1;
            }

            // O += P @ V (3-term bf16 split, V pre-transposed [dim][key])
#pragma unroll
            for (int kc = 0; kc < 4; kc++) {
                uint32_t ph[4], pl[4];
                packsplit(ph[0], pl[0], s[2 * kc][0],     s[2 * kc][1]);
                packsplit(ph[1], pl[1], s[2 * kc][2],     s[2 * kc][3]);
                packsplit(ph[2], pl[2], s[2 * kc + 1][0], s[2 * kc + 1][1]);
                packsplit(ph[3], pl[3], s[2 * kc + 1][2], s[2 * kc + 1][3]);
                uint32_t koff = ((lane & 8) << 1) + kc * 32;
#pragma unroll
                for (int dt = 0; dt < 8; dt++) {
                    uint32_t va = base + 2 * AT_PLANE + (dt * 8 + (lane & 7)) * AT_STRIDE + koff;
                    uint32_t vh[2], vl[2];
                    ldmx2(vh, va);
                    ldmx2(vl, va + AT_PLANE);
                    mma16816(oacc[dt], ph, vh);
                    mma16816(oacc[dt], ph, vl);
                    mma16816(oacc[dt], pl, vh);
                }
            }
        }
        __syncthreads();
        if (kt + 2 < ntiles) { at_load_tile(base, kh, kl, vth, vtl, head, kt + 2, tid); CP_COMMIT(); }
    }

    l0 += __shfl_xor_sync(0xffffffffu, l0, 1);
    l0 += __shfl_xor_sync(0xffffffffu, l0, 2);
    l1 += __shfl_xor_sync(0xffffffffu, l1, 1);
    l1 += __shfl_xor_sync(0xffffffffu, l1, 2);
    float i0 = 1.f / l0, i1 = 1.f / l1;
#pragma unroll
    for (int dt = 0; dt < 8; dt++) {
        int col = head * DH + dt * 8 + 2 * (lane & 3);
        float2 w0 = {oacc[dt][0] * i0, oacc[dt][1] * i0};
        float2 w1 = {oacc[dt][2] * i1, oacc[dt][3] * i1};
        *(float2*)(o + (size_t)row0 * D + col) = w0;
        *(float2*)(o + (size_t)(row0 + 8) * D + col) = w1;
    }
}

// ---------------- LayerNorm over D=1024, block per row ----------------
__global__ void ln_kernel(const float* __restrict__ x,
                          const float* __restrict__ gamma,
                          const float* __restrict__ beta,
                          float* __restrict__ y) {
    __shared__ float sh[8];
    __shared__ float stat;
    int row = blockIdx.x;
    int t = threadIdx.x;
    const float4* xr = (const float4*)(x + (size_t)row * D);
    float4 xv = xr[t];

    float s = xv.x + xv.y + xv.z + xv.w;
#pragma unroll
    for (int o = 16; o > 0; o >>= 1) s += __shfl_xor_sync(0xffffffffu, s, o);
    if ((t & 31) == 0) sh[t >> 5] = s;
    __syncthreads();
    if (t == 0) {
        float tot = 0.f;
#pragma unroll
        for (int i = 0; i < 8; i++) tot += sh[i];
        stat = tot * (1.f / (float)D);
    }
    __syncthreads();
    float mean = stat;

    float d0 = xv.x - mean, d1 = xv.y - mean, d2 = xv.z - mean, d3 = xv.w - mean;
    float sq = d0 * d0 + d1 * d1 + d2 * d2 + d3 * d3;
#pragma unroll
    for (int o = 16; o > 0; o >>= 1) sq += __shfl_xor_sync(0xffffffffu, sq, o);
    __syncthreads();
    if ((t & 31) == 0) sh[t >> 5] = sq;
    __syncthreads();
    if (t == 0) {
        float tot = 0.f;
#pragma unroll
        for (int i = 0; i < 8; i++) tot += sh[i];
        stat = rsqrtf(tot * (1.f / (float)D) + EPSF);
    }
    __syncthreads();
    float rinv = stat;

    float4 gv = ((const float4*)gamma)[t];
    float4 bv = ((const float4*)beta)[t];
    float4 o4;
    o4.x = d0 * rinv * gv.x + bv.x;
    o4.y = d1 * rinv * gv.y + bv.y;
    o4.z = d2 * rinv * gv.z + bv.z;
    o4.w = d3 * rinv * gv.w + bv.w;
    ((float4*)(y + (size_t)row * D))[t] = o4;
}

// ---------------- per-head LN (Dh=64, no bias), thread per row ----------------
__global__ void qknorm_kernel(float* __restrict__ tq, const float* __restrict__ scale) {
    int row = blockIdx.x * blockDim.x + threadIdx.x;
    float* p = tq + (size_t)row * DH;
    float4 v[16];
    float s = 0.f;
#pragma unroll
    for (int i = 0; i < 16; i++) {
        v[i] = ((const float4*)p)[i];
        s += v[i].x + v[i].y + v[i].z + v[i].w;
    }
    float mean = s * (1.f / (float)DH);
    float sq = 0.f;
#pragma unroll
    for (int i = 0; i < 16; i++) {
        v[i].x -= mean; v[i].y -= mean; v[i].z -= mean; v[i].w -= mean;
        sq += v[i].x * v[i].x + v[i].y * v[i].y + v[i].z * v[i].z + v[i].w * v[i].w;
    }
    float r = rsqrtf(sq * (1.f / (float)DH) + EPSF);
#pragma unroll
    for (int i = 0; i < 16; i++) {
        float4 sc = ((const float4*)scale)[i];
        float4 o4;
        o4.x = v[i].x * r * sc.x;
        o4.y = v[i].y * r * sc.y;
        o4.z = v[i].z * r * sc.z;
        o4.w = v[i].w * r * sc.w;
        ((float4*)p)[i] = o4;
    }
}

// ---------------- out = x + b_mo + b_ao ----------------
__global__ void init_out_kernel(const float* __restrict__ x,
                                const float* __restrict__ bmo,
                                const float* __restrict__ bao,
                                float* __restrict__ out) {
    int i = blockIdx.x * blockDim.x + threadIdx.x;
    int col = i & (D - 1);
    out[i] = x[i] + bmo[col] + bao[col];
}

// ---------------- launch ----------------
extern "C" void kernel_launch(void* const* d_in, const int* in_sizes, int n_in,
                              void* d_out, int out_size) {
    const float* x        = (const float*)d_in[0];
    // d_in[1] = mask (causal tril) handled analytically
    const float* ln_scale = (const float*)d_in[2];
    const float* ln_bias  = (const float*)d_in[3];
    const float* w_in     = (const float*)d_in[4];
    const float* b_in     = (const float*)d_in[5];
    const float* wq       = (const float*)d_in[6];
    const float* bq       = (const float*)d_in[7];
    const float* wk       = (const float*)d_in[8];
    const float* bk       = (const float*)d_in[9];
    const float* wv       = (const float*)d_in[10];
    const float* bv       = (const float*)d_in[11];
    const float* qn       = (const float*)d_in[12];
    const float* kn       = (const float*)d_in[13];
    const float* w_mo     = (const float*)d_in[14];
    const float* b_mo     = (const float*)d_in[15];
    const float* w_ao     = (const float*)d_in[16];
    const float* b_ao     = (const float*)d_in[17];
    float* out = (float*)d_out;

    float *xn, *h, *q, *k, *v, *o;
    cudaGetSymbolAddress((void**)&xn, g_xn);
    cudaGetSymbolAddress((void**)&h,  g_h);
    cudaGetSymbolAddress((void**)&q,  g_q);
    cudaGetSymbolAddress((void**)&k,  g_k);
    cudaGetSymbolAddress((void**)&v,  g_v);
    cudaGetSymbolAddress((void**)&o,  g_o);

    __nv_bfloat16 *xnh, *xnl, *hh, *hl, *oh, *ol;
    __nv_bfloat16 *qsh, *qsl, *ksh, *ksl, *vth, *vtl;
    __nv_bfloat16 *winh, *winl, *wqh, *wql, *wkh, *wkl, *wvh, *wvl, *wmoh, *wmol, *waoh, *waol;
    cudaGetSymbolAddress((void**)&xnh, g_xnh);  cudaGetSymbolAddress((void**)&xnl, g_xnl);
    cudaGetSymbolAddress((void**)&hh,  g_hh);   cudaGetSymbolAddress((void**)&hl,  g_hl);
    cudaGetSymbolAddress((void**)&oh,  g_oh);   cudaGetSymbolAddress((void**)&ol,  g_ol);
    cudaGetSymbolAddress((void**)&qsh, g_qsh);  cudaGetSymbolAddress((void**)&qsl, g_qsl);
    cudaGetSymbolAddress((void**)&ksh, g_ksh);  cudaGetSymbolAddress((void**)&ksl, g_ksl);
    cudaGetSymbolAddress((void**)&vth, g_vth);  cudaGetSymbolAddress((void**)&vtl, g_vtl);
    cudaGetSymbolAddress((void**)&winh, g_winh); cudaGetSymbolAddress((void**)&winl, g_winl);
    cudaGetSymbolAddress((void**)&wqh, g_wqh);  cudaGetSymbolAddress((void**)&wql, g_wql);
    cudaGetSymbolAddress((void**)&wkh, g_wkh);  cudaGetSymbolAddress((void**)&wkl, g_wkl);
    cudaGetSymbolAddress((void**)&wvh, g_wvh);  cudaGetSymbolAddress((void**)&wvl, g_wvl);
    cudaGetSymbolAddress((void**)&wmoh, g_wmoh); cudaGetSymbolAddress((void**)&wmol, g_wmol);
    cudaGetSymbolAddress((void**)&waoh, g_waoh); cudaGetSymbolAddress((void**)&waol, g_waol);

    cudaFuncSetAttribute(hmma_gemm<0>, cudaFuncAttributeMaxDynamicSharedMemorySize, GSMEM);
    cudaFuncSetAttribute(hmma_gemm<1>, cudaFuncAttributeMaxDynamicSharedMemorySize, GSMEM);
    cudaFuncSetAttribute(hmma_gemm<2>, cudaFuncAttributeMaxDynamicSharedMemorySize, GSMEM);
    cudaFuncSetAttribute(hmma_attn,    cudaFuncAttributeMaxDynamicSharedMemorySize, AT_SMEM);

    // weight split+transpose ([K][N] -> [N][K] bf16 hi/lo)
    splitT_kernel<<<dim3(F / 32, D / 32), dim3(32, 8)>>>(w_in, winh, winl, D, F);
    splitT_kernel<<<dim3(D / 32, D / 32), dim3(32, 8)>>>(wq, wqh, wql, D, D);
    splitT_kernel<<<dim3(D / 32, D / 32), dim3(32, 8)>>>(wk, wkh, wkl, D, D);
    splitT_kernel<<<dim3(D / 32, D / 32), dim3(32, 8)>>>(wv, wvh, wvl, D, D);
    splitT_kernel<<<dim3(D / 32, F / 32), dim3(32, 8)>>>(w_mo, wmoh, wmol, F, D);
    splitT_kernel<<<dim3(D / 32, D / 32), dim3(32, 8)>>>(w_ao, waoh, waol, D, D);

    // 1. PreNorm + split
    ln_kernel<<<S, 256>>>(x, ln_scale, ln_bias, xn);
    split_kernel<<<(S * D / 4) / 256, 256>>>(xn, xnh, xnl, 1.f);

    // 2. MLP input + GELU: h = gelu(xn @ w_in + b_in)
    hmma_gemm<1><<<dim3(F / 128, S / 128), 256, GSMEM>>>(xnh, xnl, winh, winl, b_in, h, S, F, D);
    split_kernel<<<(S * F / 4) / 256, 256>>>(h, hh, hl, 1.f);

    // 3. QKV projections
    hmma_gemm<0><<<dim3(D / 128, S / 128), 256, GSMEM>>>(xnh, xnl, wqh, wql, bq, q, S, D, D);
    hmma_gemm<0><<<dim3(D / 128, S / 128), 256, GSMEM>>>(xnh, xnl, wkh, wkl, bk, k, S, D, D);
    hmma_gemm<0><<<dim3(D / 128, S / 128), 256, GSMEM>>>(xnh, xnl, wvh, wvl, bv, v, S, D, D);

    // 4. qk-norm, then split attention operands
    qknorm_kernel<<<(S * H) / 256, 256>>>(q, qn);
    qknorm_kernel<<<(S * H) / 256, 256>>>(k, kn);
    split_kernel<<<(S * D / 4) / 256, 256>>>(q, qsh, qsl, 0.125f);   // 1/sqrt(Dh) folded in
    split_kernel<<<(S * D / 4) / 256, 256>>>(k, ksh, ksl, 1.f);
    splitT_kernel<<<dim3(D / 32, S / 32), dim3(32, 8)>>>(v, vth, vtl, S, D);  // V^T [dim][key]

    // 5. causal attention (HMMA)
    hmma_attn<<<dim3(S / 128, H), 256, AT_SMEM>>>(qsh, qsl, ksh, ksl, vth, vtl, o);
    split_kernel<<<(S * D / 4) / 256, 256>>>(o, oh, ol, 1.f);

    // 6. out = x + b_mo + b_ao, then += h@w_mo, += o@w_ao
    init_out_kernel<<<(S * D) / 256, 256>>>(x, b_mo, b_ao, out);
    hmma_gemm<2><<<dim3(D / 128, S / 128), 256, GSMEM>>>(hh, hl, wmoh, wmol, nullptr, out, S, D, F);
    hmma_gemm<2><<<dim3(D / 128, S / 128), 256, GSMEM>>>(oh, ol, waoh, waol, nullptr, out, S, D, D);
}

// round 7
// speedup vs baseline: 3.1014x; 1.0736x over previous
#include <cuda_runtime.h>
#include <cuda_bf16.h>
#include <math.h>
#include <stdint.h>

#define S 4096
#define D 1024
#define H 16
#define DH 64
#define F 4096
#define N1 7168              // F + 3*D : fused MLP-in + QKV output width
#define K2 5120              // F + D   : fused out-GEMM reduction depth
#define EPSF 1e-6f

// ---------------- scratch (device globals: alloc-free) ----------------
__device__ float g_q [S * D];
__device__ float g_k [S * D];
__device__ float g_v [S * D];

__device__ __nv_bfloat16 g_xnh[S * D], g_xnl[S * D];       // LN output planes
__device__ __nv_bfloat16 g_acth[S * K2], g_actl[S * K2];   // [h | o] planes, stride K2
__device__ __nv_bfloat16 g_qsh[S * D], g_qsl[S * D];       // q * 1/8 planes
__device__ __nv_bfloat16 g_ksh[S * D], g_ksl[S * D];       // k planes
__device__ __nv_bfloat16 g_vth[D * S], g_vtl[D * S];       // V^T planes [H*64 dims][S keys]
__device__ __nv_bfloat16 g_w1h[N1 * D], g_w1l[N1 * D];     // [w_in|wq|wk|wv]^T  [7168][1024]
__device__ __nv_bfloat16 g_w2h[D * K2], g_w2l[D * K2];     // [w_mo;w_ao]^T      [1024][5120]

// ---------------- small asm helpers (base sm_103 instructions) ----------------
__device__ __forceinline__ uint32_t smem_u32(const void* p) {
    uint32_t a;
    asm("{ .reg .u64 t; cvta.to.shared.u64 t, %1; cvt.u32.u64 %0, t; }" : "=r"(a) : "l"(p));
    return a;
}
__device__ __forceinline__ void cp16(uint32_t d, const void* s) {
    asm volatile("cp.async.cg.shared.global [%0], [%1], 16;" :: "r"(d), "l"(s));
}
#define CP_COMMIT() asm volatile("cp.async.commit_group;" ::: "memory")
#define CP_WAIT1()  asm volatile("cp.async.wait_group 1;" ::: "memory")
#define CP_WAIT0()  asm volatile("cp.async.wait_group 0;" ::: "memory")

__device__ __forceinline__ void ldmx4(uint32_t* r, uint32_t a) {
    asm volatile("ldmatrix.sync.aligned.m8n8.x4.shared.b16 {%0,%1,%2,%3}, [%4];"
                 : "=r"(r[0]), "=r"(r[1]), "=r"(r[2]), "=r"(r[3]) : "r"(a));
}
__device__ __forceinline__ void ldmx2(uint32_t* r, uint32_t a) {
    asm volatile("ldmatrix.sync.aligned.m8n8.x2.shared.b16 {%0,%1}, [%2];"
                 : "=r"(r[0]), "=r"(r[1]) : "r"(a));
}
__device__ __forceinline__ void mma16816(float* c, const uint32_t* a, const uint32_t* b) {
    asm volatile("mma.sync.aligned.m16n8k16.row.col.f32.bf16.bf16.f32 "
                 "{%0,%1,%2,%3}, {%4,%5,%6,%7}, {%8,%9}, {%0,%1,%2,%3};"
                 : "+f"(c[0]), "+f"(c[1]), "+f"(c[2]), "+f"(c[3])
                 : "r"(a[0]), "r"(a[1]), "r"(a[2]), "r"(a[3]), "r"(b[0]), "r"(b[1]));
}

__device__ __forceinline__ float gelu_f(float x) {
    float x3 = x * x * x;
    return 0.5f * x * (1.f + tanhf(0.7978845608028654f * (x + 0.044715f * x3)));
}

__device__ __forceinline__ void packsplit(uint32_t& hi, uint32_t& lo, float a, float b) {
    __nv_bfloat162 h = __floats2bfloat162_rn(a, b);
    float r0 = a - __bfloat162float(__low2bfloat16(h));
    float r1 = b - __bfloat162float(__high2bfloat16(h));
    __nv_bfloat162 l = __floats2bfloat162_rn(r0, r1);
    hi = *reinterpret_cast<uint32_t*>(&h);
    lo = *reinterpret_cast<uint32_t*>(&l);
}

// ---------------- split-transpose: in [Kd][Nd] fp32 -> out[n*ostride + k] bf16 hi/lo ----------------
__global__ void splitT_kernel(const float* __restrict__ in,
                              __nv_bfloat16* __restrict__ hi,
                              __nv_bfloat16* __restrict__ lo,
                              int Kd, int Nd, int ostride) {
    __shared__ float t[32][33];
    int n0 = blockIdx.x * 32, k0 = blockIdx.y * 32;
    int tx = threadIdx.x, ty = threadIdx.y;
#pragma unroll
    for (int j = 0; j < 4; j++)
        t[ty + j * 8][tx] = in[(size_t)(k0 + ty + j * 8) * Nd + n0 + tx];
    __syncthreads();
#pragma unroll
    for (int j = 0; j < 4; j++) {
        float v = t[tx][ty + j * 8];
        int n = n0 + ty + j * 8, k = k0 + tx;
        __nv_bfloat16 h = __float2bfloat16(v);
        hi[(size_t)n * ostride + k] = h;
        lo[(size_t)n * ostride + k] = __float2bfloat16(v - __bfloat162float(h));
    }
}

// ---------------- LayerNorm + split: x -> xn hi/lo planes ----------------
__global__ void ln_split_kernel(const float* __restrict__ x,
                                const float* __restrict__ gamma,
                                const float* __restrict__ beta,
                                uint32_t* __restrict__ yh,
                                uint32_t* __restrict__ yl) {
    __shared__ float sh[8];
    __shared__ float stat;
    int row = blockIdx.x;
    int t = threadIdx.x;
    float4 xv = ((const float4*)(x + (size_t)row * D))[t];

    float s = xv.x + xv.y + xv.z + xv.w;
#pragma unroll
    for (int o = 16; o > 0; o >>= 1) s += __shfl_xor_sync(0xffffffffu, s, o);
    if ((t & 31) == 0) sh[t >> 5] = s;
    __syncthreads();
    if (t == 0) {
        float tot = 0.f;
#pragma unroll
        for (int i = 0; i < 8; i++) tot += sh[i];
        stat = tot * (1.f / (float)D);
    }
    __syncthreads();
    float mean = stat;

    float d0 = xv.x - mean, d1 = xv.y - mean, d2 = xv.z - mean, d3 = xv.w - mean;
    float sq = d0 * d0 + d1 * d1 + d2 * d2 + d3 * d3;
#pragma unroll
    for (int o = 16; o > 0; o >>= 1) sq += __shfl_xor_sync(0xffffffffu, sq, o);
    __syncthreads();
    if ((t & 31) == 0) sh[t >> 5] = sq;
    __syncthreads();
    if (t == 0) {
        float tot = 0.f;
#pragma unroll
        for (int i = 0; i < 8; i++) tot += sh[i];
        stat = rsqrtf(tot * (1.f / (float)D) + EPSF);
    }
    __syncthreads();
    float rinv = stat;

    float4 gv = ((const float4*)gamma)[t];
    float4 bv = ((const float4*)beta)[t];
    float v0 = d0 * rinv * gv.x + bv.x;
    float v1 = d1 * rinv * gv.y + bv.y;
    float v2 = d2 * rinv * gv.z + bv.z;
    float v3 = d3 * rinv * gv.w + bv.w;
    uint32_t h0, l0, h1, l1;
    packsplit(h0, l0, v0, v1);
    packsplit(h1, l1, v2, v3);
    int idx = row * (D / 2) + 2 * t;
    yh[idx] = h0; yh[idx + 1] = h1;
    yl[idx] = l0; yl[idx + 1] = l1;
}

// ---------------- per-head LN + scale + split, thread per (s,h) row ----------------
__global__ void qknorm_split(const float* __restrict__ tq, const float* __restrict__ scale,
                             uint32_t* __restrict__ oh, uint32_t* __restrict__ ol, float sc) {
    int row = blockIdx.x * blockDim.x + threadIdx.x;
    const float* p = tq + (size_t)row * DH;
    float4 v[16];
    float s = 0.f;
#pragma unroll
    for (int i = 0; i < 16; i++) {
        v[i] = ((const float4*)p)[i];
        s += v[i].x + v[i].y + v[i].z + v[i].w;
    }
    float mean = s * (1.f / (float)DH);
    float sq = 0.f;
#pragma unroll
    for (int i = 0; i < 16; i++) {
        v[i].x -= mean; v[i].y -= mean; v[i].z -= mean; v[i].w -= mean;
        sq += v[i].x * v[i].x + v[i].y * v[i].y + v[i].z * v[i].z + v[i].w * v[i].w;
    }
    float r = rsqrtf(sq * (1.f / (float)DH) + EPSF) * sc;
#pragma unroll
    for (int i = 0; i < 16; i++) {
        float4 scv = ((const float4*)scale)[i];
        uint32_t h0, l0, h1, l1;
        packsplit(h0, l0, v[i].x * r * scv.x, v[i].y * r * scv.y);
        packsplit(h1, l1, v[i].z * r * scv.z, v[i].w * r * scv.w);
        int idx = row * (DH / 2) + 2 * i;
        oh[idx] = h0; oh[idx + 1] = h1;
        ol[idx] = l0; ol[idx + 1] = l1;
    }
}

// ================= HMMA GEMM core =================
#define GBM 128
#define GBN 128
#define GBK 32
#define PLANE_B (128 * 40 * 2)
#define BUF_B   (4 * PLANE_B)
#define GSMEM   (2 * BUF_B)

__device__ __forceinline__ void issue_chunk(
    uint32_t base,
    const __nv_bfloat16* Ah, const __nv_bfloat16* Al,
    const __nv_bfloat16* Bh, const __nv_bfloat16* Bl,
    int bm, int bn, int kc, int K, int tid)
{
    int row  = tid >> 1;
    int half = tid & 1;
    uint32_t doff = row * 80 + half * 32;
    size_t aoff = (size_t)(bm + row) * K + kc + half * 16;
    size_t boff = (size_t)(bn + row) * K + kc + half * 16;
    cp16(base + doff,                    Ah + aoff);
    cp16(base + doff + 16,               Ah + aoff + 8);
    cp16(base + PLANE_B + doff,          Al + aoff);
    cp16(base + PLANE_B + doff + 16,     Al + aoff + 8);
    cp16(base + 2 * PLANE_B + doff,      Bh + boff);
    cp16(base + 2 * PLANE_B + doff + 16, Bh + boff + 8);
    cp16(base + 3 * PLANE_B + doff,      Bl + boff);
    cp16(base + 3 * PLANE_B + doff + 16, Bl + boff + 8);
}

// mainloop: fills acc[4][4][4] for (wm,wn) warp tile. Safe ordering: wait0 -> sync -> issue -> compute.
__device__ __forceinline__ void hmma_mainloop(
    uint32_t sb, float acc[4][4][4],
    const __nv_bfloat16* Ah, const __nv_bfloat16* Al,
    const __nv_bfloat16* Bh, const __nv_bfloat16* Bl,
    int bm, int bn, int K, int tid, int lane, int wm, int wn)
{
    uint32_t a_off = (uint32_t)((wm * 64 + (lane & 7) + (lane & 8)) * 80 + ((lane >> 4) << 4));
    uint32_t b_off = (uint32_t)((wn * 32 + (lane & 7)) * 80 + ((lane & 8) << 1));

    int nk = K / GBK;
    issue_chunk(sb, Ah, Al, Bh, Bl, bm, bn, 0, K, tid);
    CP_COMMIT();

    for (int c = 0; c < nk; c++) {
        CP_WAIT0();
        __syncthreads();
        if (c + 1 < nk) {
            issue_chunk(sb + ((c + 1) & 1) * BUF_B, Ah, Al, Bh, Bl, bm, bn, (c + 1) * GBK, K, tid);
            CP_COMMIT();
        }
        uint32_t base = sb + (c & 1) * BUF_B;
        uint32_t aH = base, aL = base + PLANE_B;
        uint32_t bH = base + 2 * PLANE_B, bL = base + 3 * PLANE_B;

#pragma unroll
        for (int k16 = 0; k16 < 2; k16++) {
            uint32_t kb = k16 * 32;
            uint32_t ahf[4][4], bfr[4][2];
#pragma unroll
            for (int mt = 0; mt < 4; mt++) ldmx4(ahf[mt], aH + a_off + mt * 1280 + kb);
#pragma unroll
            for (int nt = 0; nt < 4; nt++) ldmx2(bfr[nt], bH + b_off + nt * 640 + kb);
#pragma unroll
            for (int mt = 0; mt < 4; mt++)
#pragma unroll
                for (int nt = 0; nt < 4; nt++) mma16816(acc[mt][nt], ahf[mt], bfr[nt]);

            uint32_t alf[4][4];
#pragma unroll
            for (int mt = 0; mt < 4; mt++) ldmx4(alf[mt], aL + a_off + mt * 1280 + kb);
#pragma unroll
            for (int mt = 0; mt < 4; mt++)
#pragma unroll
                for (int nt = 0; nt < 4; nt++) mma16816(acc[mt][nt], alf[mt], bfr[nt]);

#pragma unroll
            for (int nt = 0; nt < 4; nt++) ldmx2(bfr[nt], bL + b_off + nt * 640 + kb);
#pragma unroll
            for (int mt = 0; mt < 4; mt++)
#pragma unroll
                for (int nt = 0; nt < 4; nt++) mma16816(acc[mt][nt], ahf[mt], bfr[nt]);
        }
        __syncthreads();
    }
}

// ---- fused GEMM 1: [xn] @ [w_in|wq|wk|wv]^T over N=7168 ----
// n < 4096          : gelu(acc+b_in) -> split planes into g_act[:, n]
// 4096 <= n < 5120  : acc+bq -> q fp32
// 5120 <= n < 6144  : acc+bk -> k fp32
// 6144 <= n < 7168  : acc+bv -> v fp32
__global__ void __launch_bounds__(256, 2) hmma_gemm_f1(
    const __nv_bfloat16* __restrict__ Ah, const __nv_bfloat16* __restrict__ Al,
    const __nv_bfloat16* __restrict__ Bh, const __nv_bfloat16* __restrict__ Bl,
    const float* __restrict__ b_in, const float* __restrict__ bq,
    const float* __restrict__ bk, const float* __restrict__ bv,
    uint32_t* __restrict__ acth, uint32_t* __restrict__ actl,
    float* __restrict__ qf, float* __restrict__ kf, float* __restrict__ vf)
{
    extern __shared__ __align__(128) char smem[];
    uint32_t sb = smem_u32(smem);
    int tid = threadIdx.x, lane = tid & 31, wid = tid >> 5;
    int wm = wid >> 2, wn = wid & 3;
    int bm = blockIdx.y * GBM, bn = blockIdx.x * GBN;

    float acc[4][4][4];
#pragma unroll
    for (int i = 0; i < 4; i++)
#pragma unroll
        for (int j = 0; j < 4; j++)
#pragma unroll
            for (int r = 0; r < 4; r++) acc[i][j][r] = 0.f;

    hmma_mainloop(sb, acc, Ah, Al, Bh, Bl, bm, bn, D, tid, lane, wm, wn);

    int lr = lane >> 2, lc = (lane & 3) * 2;
#pragma unroll
    for (int mt = 0; mt < 4; mt++) {
#pragma unroll
        for (int nt = 0; nt < 4; nt++) {
            float* a = acc[mt][nt];
            int m0 = bm + wm * 64 + mt * 16 + lr;
            int n0 = bn + wn * 32 + nt * 8 + lc;
            if (n0 < F) {
                float b0 = b_in[n0], b1 = b_in[n0 + 1];
                float v0 = gelu_f(a[0] + b0), v1 = gelu_f(a[1] + b1);
                float v2 = gelu_f(a[2] + b0), v3 = gelu_f(a[3] + b1);
                uint32_t h0, l0, h1, l1;
                packsplit(h0, l0, v0, v1);
                packsplit(h1, l1, v2, v3);
                size_t i0 = (size_t)m0 * (K2 / 2) + (n0 >> 1);
                size_t i1 = (size_t)(m0 + 8) * (K2 / 2) + (n0 >> 1);
                acth[i0] = h0; actl[i0] = l0;
                acth[i1] = h1; actl[i1] = l1;
            } else {
                int r = (n0 - F) >> 10;
                int c = (n0 - F) & (D - 1);
                const float* bp = (r == 0) ? bq : (r == 1) ? bk : bv;
                float* dst = (r == 0) ? qf : (r == 1) ? kf : vf;
                float b0 = bp[c], b1 = bp[c + 1];
                float2 w0 = {a[0] + b0, a[1] + b1};
                float2 w1 = {a[2] + b0, a[3] + b1};
                *(float2*)(dst + (size_t)m0 * D + c) = w0;
                *(float2*)(dst + (size_t)(m0 + 8) * D + c) = w1;
            }
        }
    }
}

// ---- GEMM 2: out += act @ [w_mo;w_ao]^T (K=5120) ----
__global__ void __launch_bounds__(256, 2) hmma_gemm_acc(
    const __nv_bfloat16* __restrict__ Ah, const __nv_bfloat16* __restrict__ Al,
    const __nv_bfloat16* __restrict__ Bh, const __nv_bfloat16* __restrict__ Bl,
    float* __restrict__ C, int N, int K)
{
    extern __shared__ __align__(128) char smem[];
    uint32_t sb = smem_u32(smem);
    int tid = threadIdx.x, lane = tid & 31, wid = tid >> 5;
    int wm = wid >> 2, wn = wid & 3;
    int bm = blockIdx.y * GBM, bn = blockIdx.x * GBN;

    float acc[4][4][4];
#pragma unroll
    for (int i = 0; i < 4; i++)
#pragma unroll
        for (int j = 0; j < 4; j++)
#pragma unroll
            for (int r = 0; r < 4; r++) acc[i][j][r] = 0.f;

    hmma_mainloop(sb, acc, Ah, Al, Bh, Bl, bm, bn, K, tid, lane, wm, wn);

    int lr = lane >> 2, lc = (lane & 3) * 2;
#pragma unroll
    for (int mt = 0; mt < 4; mt++) {
#pragma unroll
        for (int nt = 0; nt < 4; nt++) {
            float* a = acc[mt][nt];
            int m0 = bm + wm * 64 + mt * 16 + lr;
            int n0 = bn + wn * 32 + nt * 8 + lc;
            float2* p0 = (float2*)(C + (size_t)m0 * N + n0);
            float2* p1 = (float2*)(C + (size_t)(m0 + 8) * N + n0);
            float2 v0 = *p0, v1 = *p1;
            v0.x += a[0]; v0.y += a[1];
            v1.x += a[2]; v1.y += a[3];
            *p0 = v0; *p1 = v1;
        }
    }
}

// ================= HMMA flash attention (o written as split planes into act buffer) =================
#define AT_STRIDE 144
#define AT_PLANE (64 * AT_STRIDE)
#define AT_BUF   (4 * AT_PLANE)
#define AT_SMEM  (2 * AT_BUF)

__device__ __forceinline__ void at_load_tile(
    uint32_t dst, const __nv_bfloat16* kh, const __nv_bfloat16* kl,
    const __nv_bfloat16* vth, const __nv_bfloat16* vtl,
    int head, int kt, int tid)
{
    int row = tid >> 2, q4 = tid & 3;
    size_t koff = (size_t)(kt * 64 + row) * D + head * DH + q4 * 16;
    uint32_t d = dst + row * AT_STRIDE + q4 * 32;
    cp16(d,                    kh + koff);
    cp16(d + 16,               kh + koff + 8);
    cp16(d + AT_PLANE,         kl + koff);
    cp16(d + AT_PLANE + 16,    kl + koff + 8);
    size_t voff = (size_t)(head * DH + row) * S + kt * 64 + q4 * 16;
    cp16(d + 2 * AT_PLANE,      vth + voff);
    cp16(d + 2 * AT_PLANE + 16, vth + voff + 8);
    cp16(d + 3 * AT_PLANE,      vtl + voff);
    cp16(d + 3 * AT_PLANE + 16, vtl + voff + 8);
}

__global__ void __launch_bounds__(256, 1) hmma_attn(
    const __nv_bfloat16* __restrict__ qh, const __nv_bfloat16* __restrict__ ql,
    const __nv_bfloat16* __restrict__ kh, const __nv_bfloat16* __restrict__ kl,
    const __nv_bfloat16* __restrict__ vth, const __nv_bfloat16* __restrict__ vtl,
    uint32_t* __restrict__ acth, uint32_t* __restrict__ actl)
{
    extern __shared__ __align__(128) char smem[];
    uint32_t sb = smem_u32(smem);
    int tid = threadIdx.x, lane = tid & 31, wid = tid >> 5;
    int qt = (int)gridDim.x - 1 - (int)blockIdx.x;   // heavy tiles first
    int head = blockIdx.y;
    int ntiles = 2 * qt + 2;

    {
        int row = tid >> 1, half = tid & 1;
        const __nv_bfloat16* s0 = qh + (size_t)(qt * 128 + row) * D + head * DH + half * 32;
        const __nv_bfloat16* s1 = ql + (size_t)(qt * 128 + row) * D + head * DH + half * 32;
        uint32_t dq = sb + AT_BUF + row * AT_STRIDE + half * 64;
        cp16(dq,      s0); cp16(dq + 16, s0 + 8);
        cp16(dq + 32, s0 + 16); cp16(dq + 48, s0 + 24);
        uint32_t dl = dq + 2 * AT_PLANE;
        cp16(dl,      s1); cp16(dl + 16, s1 + 8);
        cp16(dl + 32, s1 + 16); cp16(dl + 48, s1 + 24);
    }
    CP_COMMIT();
    at_load_tile(sb, kh, kl, vth, vtl, head, 0, tid);
    CP_COMMIT();
    CP_WAIT0();
    __syncthreads();

    uint32_t qhf[4][4], qlf[4][4];
#pragma unroll
    for (int kc = 0; kc < 4; kc++) {
        uint32_t a = sb + AT_BUF + (wid * 16 + (lane & 15)) * AT_STRIDE
                   + ((lane >> 4) & 1) * 16 + kc * 32;
        ldmx4(qhf[kc], a);
        ldmx4(qlf[kc], a + 2 * AT_PLANE);
    }
    __syncthreads();
    if (ntiles > 1) { at_load_tile(sb + AT_BUF, kh, kl, vth, vtl, head, 1, tid); CP_COMMIT(); }

    float oacc[8][4];
#pragma unroll
    for (int i = 0; i < 8; i++)
#pragma unroll
        for (int j = 0; j < 4; j++) oacc[i][j] = 0.f;
    float m0 = -INFINITY, m1 = -INFINITY, l0 = 0.f, l1 = 0.f;
    int row0 = qt * 128 + wid * 16 + (lane >> 2);

    for (int kt = 0; kt < ntiles; kt++) {
        if (kt + 1 < ntiles) CP_WAIT1(); else CP_WAIT0();
        __syncthreads();
        uint32_t base = sb + (kt & 1) * AT_BUF;

        if (kt * 64 <= qt * 128 + wid * 16 + 15) {
            float s[8][4];
#pragma unroll
            for (int i = 0; i < 8; i++)
#pragma unroll
                for (int j = 0; j < 4; j++) s[i][j] = 0.f;

#pragma unroll
            for (int kc = 0; kc < 4; kc++) {
                uint32_t koff = ((lane & 8) << 1) + kc * 32;
#pragma unroll
                for (int nt = 0; nt < 8; nt++) {
                    uint32_t ka = base + (nt * 8 + (lane & 7)) * AT_STRIDE + koff;
                    uint32_t bh[2], bl[2];
                    ldmx2(bh, ka);
                    ldmx2(bl, ka + AT_PLANE);
                    mma16816(s[nt], qhf[kc], bh);
                    mma16816(s[nt], qhf[kc], bl);
                    mma16816(s[nt], qlf[kc], bh);
                }
            }

            if (kt >= 2 * qt) {
#pragma unroll
                for (int nt = 0; nt < 8; nt++) {
                    int c = kt * 64 + nt * 8 + 2 * (lane & 3);
                    if (c     > row0)     s[nt][0] = -INFINITY;
                    if (c + 1 > row0)     s[nt][1] = -INFINITY;
                    if (c     > row0 + 8) s[nt][2] = -INFINITY;
                    if (c + 1 > row0 + 8) s[nt][3] = -INFINITY;
                }
            }

            float mx0 = -INFINITY, mx1 = -INFINITY;
#pragma unroll
            for (int nt = 0; nt < 8; nt++) {
                mx0 = fmaxf(mx0, fmaxf(s[nt][0], s[nt][1]));
                mx1 = fmaxf(mx1, fmaxf(s[nt][2], s[nt][3]));
            }
            mx0 = fmaxf(mx0, __shfl_xor_sync(0xffffffffu, mx0, 1));
            mx0 = fmaxf(mx0, __shfl_xor_sync(0xffffffffu, mx0, 2));
            mx1 = fmaxf(mx1, __shfl_xor_sync(0xffffffffu, mx1, 1));
            mx1 = fmaxf(mx1, __shfl_xor_sync(0xffffffffu, mx1, 2));
            float nm0 = fmaxf(m0, mx0), nm1 = fmaxf(m1, mx1);
            float a0 = __expf(m0 - nm0), a1 = __expf(m1 - nm1);
            m0 = nm0; m1 = nm1;
            float ps0 = 0.f, ps1 = 0.f;
#pragma unroll
            for (int nt = 0; nt < 8; nt++) {
                s[nt][0] = __expf(s[nt][0] - m0); ps0 += s[nt][0];
                s[nt][1] = __expf(s[nt][1] - m0); ps0 += s[nt][1];
                s[nt][2] = __expf(s[nt][2] - m1); ps1 += s[nt][2];
                s[nt][3] = __expf(s[nt][3] - m1); ps1 += s[nt][3];
            }
            l0 = l0 * a0 + ps0;
            l1 = l1 * a1 + ps1;
#pragma unroll
            for (int dt = 0; dt < 8; dt++) {
                oacc[dt][0] *= a0; oacc[dt][1] *= a0;
                oacc[dt][2] *= a1; oacc[dt][3] *= a1;
            }

#pragma unroll
            for (int kc = 0; kc < 4; kc++) {
                uint32_t ph[4], pl[4];
                packsplit(ph[0], pl[0], s[2 * kc][0],     s[2 * kc][1]);
                packsplit(ph[1], pl[1], s[2 * kc][2],     s[2 * kc][3]);
                packsplit(ph[2], pl[2], s[2 * kc + 1][0], s[2 * kc + 1][1]);
                packsplit(ph[3], pl[3], s[2 * kc + 1][2], s[2 * kc + 1][3]);
                uint32_t koff = ((lane & 8) << 1) + kc * 32;
#pragma unroll
                for (int dt = 0; dt < 8; dt++) {
                    uint32_t va = base + 2 * AT_PLANE + (dt * 8 + (lane & 7)) * AT_STRIDE + koff;
                    uint32_t vh[2], vl[2];
                    ldmx2(vh, va);
                    ldmx2(vl, va + AT_PLANE);
                    mma16816(oacc[dt], ph, vh);
                    mma16816(oacc[dt], ph, vl);
                    mma16816(oacc[dt], pl, vh);
                }
            }
        }
        __syncthreads();
        if (kt + 2 < ntiles) { at_load_tile(base, kh, kl, vth, vtl, head, kt + 2, tid); CP_COMMIT(); }
    }

    l0 += __shfl_xor_sync(0xffffffffu, l0, 1);
    l0 += __shfl_xor_sync(0xffffffffu, l0, 2);
    l1 += __shfl_xor_sync(0xffffffffu, l1, 1);
    l1 += __shfl_xor_sync(0xffffffffu, l1, 2);
    float i0 = 1.f / l0, i1 = 1.f / l1;
#pragma unroll
    for (int dt = 0; dt < 8; dt++) {
        int col = F + head * DH + dt * 8 + 2 * (lane & 3);   // into act[:, 4096 + ...]
        uint32_t h0, lo0, h1, lo1;
        packsplit(h0, lo0, oacc[dt][0] * i0, oacc[dt][1] * i0);
        packsplit(h1, lo1, oacc[dt][2] * i1, oacc[dt][3] * i1);
        size_t i0x = (size_t)row0 * (K2 / 2) + (col >> 1);
        size_t i1x = (size_t)(row0 + 8) * (K2 / 2) + (col >> 1);
        acth[i0x] = h0; actl[i0x] = lo0;
        acth[i1x] = h1; actl[i1x] = lo1;
    }
}

// ---------------- out = x + b_mo + b_ao ----------------
__global__ void init_out_kernel(const float* __restrict__ x,
                                const float* __restrict__ bmo,
                                const float* __restrict__ bao,
                                float* __restrict__ out) {
    int i = blockIdx.x * blockDim.x + threadIdx.x;
    int col = i & (D - 1);
    out[i] = x[i] + bmo[col] + bao[col];
}

// ---------------- launch ----------------
extern "C" void kernel_launch(void* const* d_in, const int* in_sizes, int n_in,
                              void* d_out, int out_size) {
    const float* x        = (const float*)d_in[0];
    // d_in[1] = mask (causal tril) handled analytically
    const float* ln_scale = (const float*)d_in[2];
    const float* ln_bias  = (const float*)d_in[3];
    const float* w_in     = (const float*)d_in[4];
    const float* b_in     = (const float*)d_in[5];
    const float* wq       = (const float*)d_in[6];
    const float* bq       = (const float*)d_in[7];
    const float* wk       = (const float*)d_in[8];
    const float* bk       = (const float*)d_in[9];
    const float* wv       = (const float*)d_in[10];
    const float* bv       = (const float*)d_in[11];
    const float* qn       = (const float*)d_in[12];
    const float* kn       = (const float*)d_in[13];
    const float* w_mo     = (const float*)d_in[14];
    const float* b_mo     = (const float*)d_in[15];
    const float* w_ao     = (const float*)d_in[16];
    const float* b_ao     = (const float*)d_in[17];
    float* out = (float*)d_out;

    float *q, *k, *v;
    cudaGetSymbolAddress((void**)&q, g_q);
    cudaGetSymbolAddress((void**)&k, g_k);
    cudaGetSymbolAddress((void**)&v, g_v);

    __nv_bfloat16 *xnh, *xnl, *acth, *actl, *qsh, *qsl, *ksh, *ksl, *vth, *vtl;
    __nv_bfloat16 *w1h, *w1l, *w2h, *w2l;
    cudaGetSymbolAddress((void**)&xnh, g_xnh);   cudaGetSymbolAddress((void**)&xnl, g_xnl);
    cudaGetSymbolAddress((void**)&acth, g_acth); cudaGetSymbolAddress((void**)&actl, g_actl);
    cudaGetSymbolAddress((void**)&qsh, g_qsh);   cudaGetSymbolAddress((void**)&qsl, g_qsl);
    cudaGetSymbolAddress((void**)&ksh, g_ksh);   cudaGetSymbolAddress((void**)&ksl, g_ksl);
    cudaGetSymbolAddress((void**)&vth, g_vth);   cudaGetSymbolAddress((void**)&vtl, g_vtl);
    cudaGetSymbolAddress((void**)&w1h, g_w1h);   cudaGetSymbolAddress((void**)&w1l, g_w1l);
    cudaGetSymbolAddress((void**)&w2h, g_w2h);   cudaGetSymbolAddress((void**)&w2l, g_w2l);

    cudaFuncSetAttribute(hmma_gemm_f1,  cudaFuncAttributeMaxDynamicSharedMemorySize, GSMEM);
    cudaFuncSetAttribute(hmma_gemm_acc, cudaFuncAttributeMaxDynamicSharedMemorySize, GSMEM);
    cudaFuncSetAttribute(hmma_attn,     cudaFuncAttributeMaxDynamicSharedMemorySize, AT_SMEM);

    // ---- weight packing: [w_in|wq|wk|wv]^T -> g_w1 (7168x1024); [w_mo;w_ao]^T -> g_w2 (1024x5120)
    splitT_kernel<<<dim3(F / 32, D / 32), dim3(32, 8)>>>(w_in, w1h, w1l, D, F, D);
    splitT_kernel<<<dim3(D / 32, D / 32), dim3(32, 8)>>>(wq, w1h + (size_t)F * D, w1l + (size_t)F * D, D, D, D);
    splitT_kernel<<<dim3(D / 32, D / 32), dim3(32, 8)>>>(wk, w1h + (size_t)(F + D) * D, w1l + (size_t)(F + D) * D, D, D, D);
    splitT_kernel<<<dim3(D / 32, D / 32), dim3(32, 8)>>>(wv, w1h + (size_t)(F + 2 * D) * D, w1l + (size_t)(F + 2 * D) * D, D, D, D);
    splitT_kernel<<<dim3(D / 32, F / 32), dim3(32, 8)>>>(w_mo, w2h, w2l, F, D, K2);
    splitT_kernel<<<dim3(D / 32, D / 32), dim3(32, 8)>>>(w_ao, w2h + F, w2l + F, D, D, K2);

    // 1. PreNorm (writes split planes directly)
    ln_split_kernel<<<S, 256>>>(x, ln_scale, ln_bias, (uint32_t*)xnh, (uint32_t*)xnl);

    // 2. fused MLP-in(+GELU+split) & QKV GEMM
    hmma_gemm_f1<<<dim3(N1 / 128, S / 128), 256, GSMEM>>>(
        xnh, xnl, w1h, w1l, b_in, bq, bk, bv,
        (uint32_t*)acth, (uint32_t*)actl, q, k, v);

    // 3. qk-norm + scale + split; V split-transpose
    qknorm_split<<<(S * H) / 256, 256>>>(q, qn, (uint32_t*)qsh, (uint32_t*)qsl, 0.125f);
    qknorm_split<<<(S * H) / 256, 256>>>(k, kn, (uint32_t*)ksh, (uint32_t*)ksl, 1.f);
    splitT_kernel<<<dim3(D / 32, S / 32), dim3(32, 8)>>>(v, vth, vtl, S, D, S);

    // 4. causal attention (writes split planes into act[:, 4096:5120])
    hmma_attn<<<dim3(S / 128, H), 256, AT_SMEM>>>(qsh, qsl, ksh, ksl, vth, vtl,
                                                  (uint32_t*)acth, (uint32_t*)actl);

    // 5. out = x + b_mo + b_ao, then += act @ [w_mo;w_ao]
    init_out_kernel<<<(S * D) / 256, 256>>>(x, b_mo, b_ao, out);
    hmma_gemm_acc<<<dim3(D / 128, S / 128), 256, GSMEM>>>(acth, actl, w2h, w2l, out, D, K2);
}